// round 5
// baseline (speedup 1.0000x reference)
#include <cuda_runtime.h>
#include <cuda_bf16.h>
#include <mma.h>
#include <math.h>
#include <stdint.h>

using namespace nvcuda;

#define BATCH 4
#define CH    256
#define CKDIM 64
#define NPIX  4096
#define EPS   1e-5f

#define LDQ   72      // Q/K smem leading dim (bf16)
#define LDV   136     // V / q smem leading dim (bf16)
#define LDSF  132     // S smem leading dim (fp32)

#define DINL __device__ __forceinline__

// ---------------- device scratch (static, allocation-free) ----------------
__device__ __align__(16) float g_scale[CH];
__device__ __align__(16) float g_shift[CH];
__device__ __align__(16) float g_sx  [BATCH * CH];
__device__ __align__(16) float g_base[BATCH * CH];                        // alpha*0.5*SumV
__device__ __align__(16) float2 g_stats[(size_t)BATCH * NPIX];            // (rowmax, 1/Z)
__device__ __align__(16) __nv_bfloat16 g_Qb[BATCH * NPIX * CKDIM];        // [b][i][64]
__device__ __align__(16) __nv_bfloat16 g_Kb[BATCH * NPIX * CKDIM];        // [b][j][64]
__device__ __align__(16) __nv_bfloat16 g_VH[(size_t)BATCH * CH * NPIX];   // [b][c][n]

// ---------------- portable async-copy helpers (sm_80+ PTX) -----------------
DINL uint32_t smem_u32(const void* p) {
    uint32_t a;
    asm("{ .reg .u64 t; cvta.to.shared.u64 t, %1; cvt.u32.u64 %0, t; }"
        : "=r"(a) : "l"(p));
    return a;
}
DINL void cpa16(uint32_t dst, const void* src) {
    asm volatile("cp.async.cg.shared.global [%0], [%1], 16;"
                 :: "r"(dst), "l"(src) : "memory");
}
DINL void cpa_commit() { asm volatile("cp.async.commit_group;" ::: "memory"); }
template<int N> DINL void cpa_wait() {
    asm volatile("cp.async.wait_group %0;" :: "n"(N) : "memory");
}

// ---------------- kernel 0: fold BN ----------------
__global__ void prep_kernel(const float* __restrict__ gamma,
                            const float* __restrict__ beta,
                            const float* __restrict__ mean,
                            const float* __restrict__ var) {
    int c = threadIdx.x;
    if (c < CH) {
        float s = gamma[c] * rsqrtf(var[c] + EPS);
        g_scale[c] = s;
        g_shift[c] = beta[c] - mean[c] * s;
    }
}

// ---------------- kernel 0b: column sums of x -> sx[b][c] -------------------
__global__ void colsum_kernel(const float* __restrict__ x) {
    const int c = blockIdx.x, b = blockIdx.y;
    const float* row = x + ((size_t)b * CH + c) * NPIX;
    const int t = threadIdx.x;
    float s = 0.f;
    #pragma unroll
    for (int q = 0; q < 16; ++q) s += row[t + q * 256];
    #pragma unroll
    for (int o = 16; o; o >>= 1) s += __shfl_xor_sync(0xffffffffu, s, o);
    __shared__ float ws[8];
    if ((t & 31) == 0) ws[t >> 5] = s;
    __syncthreads();
    if (t == 0) {
        float tot = 0.f;
        #pragma unroll
        for (int w = 0; w < 8; ++w) tot += ws[w];
        g_sx[b * CH + c] = tot;
    }
}

// ---------------- kernel 0c: base[b][c] = alpha*0.5*(Wd[c,:]·sx[b,:] + N*bd) -
__global__ void sumv_kernel(const float* __restrict__ Wd,
                            const float* __restrict__ bd,
                            const float* __restrict__ alpha) {
    const int b = blockIdx.x;
    const int c = threadIdx.x;
    __shared__ float sxs[CH];
    sxs[c] = g_sx[b * CH + c];
    __syncthreads();
    float dot = 0.f;
    const float* wr = Wd + (size_t)c * CH;
    #pragma unroll 8
    for (int k = 0; k < CH; ++k) dot += wr[k] * sxs[k];
    g_base[b * CH + c] = alpha[0] * 0.5f * (dot + (float)NPIX * bd[c]);
}

// ---------------- kernel 1a: Q/K projection (BN folded), bf16 out [b][n][64]
__global__ void projqk_kernel(const float* __restrict__ x,
                              const float* __restrict__ W,
                              const float* __restrict__ bias,
                              __nv_bfloat16* __restrict__ out) {
    __shared__ float As[16][65];
    __shared__ float Bs[16][65];
    const int b  = blockIdx.z;
    const int n0 = blockIdx.x * 64;
    const float* xb = x + (size_t)b * CH * NPIX;
    const int tid = threadIdx.x;
    const int tk = tid & 15;
    const int tn = tid >> 4;

    float acc[4][4] = {};
    for (int c0 = 0; c0 < CH; c0 += 16) {
        {
            int nn = tid & 63, cb = tid >> 6;
            #pragma unroll
            for (int r = 0; r < 4; ++r) {
                int cc = cb + r * 4;
                float v = xb[(size_t)(c0 + cc) * NPIX + n0 + nn];
                As[cc][nn] = v * g_scale[c0 + cc] + g_shift[c0 + cc];
            }
        }
        {
            int cc = tid & 15, kb = tid >> 4;
            #pragma unroll
            for (int r = 0; r < 4; ++r) {
                int kk = kb + r * 16;
                Bs[cc][kk] = W[(size_t)kk * CH + c0 + cc];
            }
        }
        __syncthreads();
        #pragma unroll
        for (int cc = 0; cc < 16; ++cc) {
            float a[4], bv[4];
            #pragma unroll
            for (int i = 0; i < 4; ++i) a[i]  = As[cc][tn + i * 16];
            #pragma unroll
            for (int j = 0; j < 4; ++j) bv[j] = Bs[cc][tk + j * 16];
            #pragma unroll
            for (int i = 0; i < 4; ++i)
                #pragma unroll
                for (int j = 0; j < 4; ++j) acc[i][j] += a[i] * bv[j];
        }
        __syncthreads();
    }
    __nv_bfloat16* ob = out + (size_t)b * NPIX * CKDIM;
    #pragma unroll
    for (int i = 0; i < 4; ++i) {
        int n = n0 + tn + i * 16;
        #pragma unroll
        for (int j = 0; j < 4; ++j) {
            int k = tk + j * 16;
            ob[(size_t)n * CKDIM + k] = __float2bfloat16(acc[i][j] + bias[k]);
        }
    }
}

// ---------------- kernel 1b: V projection, bf16 [b][d][n], x read ONCE ------
// CTA: 64 n x 256 d; 256 threads; micro 16d x 4n per thread
__global__ __launch_bounds__(256) void projv_kernel(const float* __restrict__ x,
                                                    const float* __restrict__ W,
                                                    const float* __restrict__ bias,
                                                    __nv_bfloat16* __restrict__ vh) {
    __shared__ float As[16][65];    // c x n
    __shared__ float Bs[16][264];   // c x d
    const int b  = blockIdx.y;
    const int n0 = blockIdx.x * 64;
    const float* xb = x + (size_t)b * CH * NPIX;
    const int tid = threadIdx.x;
    const int tn = tid & 15;
    const int td = tid >> 4;

    float acc[16][4] = {};
    for (int c0 = 0; c0 < CH; c0 += 16) {
        {
            int nn = tid & 63, cb = tid >> 6;
            #pragma unroll
            for (int r = 0; r < 4; ++r) {
                int cc = cb + r * 4;
                As[cc][nn] = xb[(size_t)(c0 + cc) * NPIX + n0 + nn];
            }
        }
        {
            int cc = tid & 15, db = tid >> 4;
            #pragma unroll
            for (int r = 0; r < 16; ++r) {
                int dd = db + r * 16;
                Bs[cc][dd] = W[(size_t)dd * CH + c0 + cc];
            }
        }
        __syncthreads();
        #pragma unroll
        for (int cc = 0; cc < 16; ++cc) {
            float a[4], w[16];
            #pragma unroll
            for (int j = 0; j < 4; ++j) a[j] = As[cc][tn + j * 16];
            #pragma unroll
            for (int i = 0; i < 16; ++i) w[i] = Bs[cc][td + i * 16];
            #pragma unroll
            for (int i = 0; i < 16; ++i)
                #pragma unroll
                for (int j = 0; j < 4; ++j) acc[i][j] += w[i] * a[j];
        }
        __syncthreads();
    }
    #pragma unroll
    for (int i = 0; i < 16; ++i) {
        int d = td + i * 16;
        float bd_ = bias[d];
        #pragma unroll
        for (int j = 0; j < 4; ++j) {
            int n = n0 + tn + j * 16;
            vh[((size_t)b * CH + d) * NPIX + n] = __float2bfloat16(acc[i][j] + bd_);
        }
    }
}

// ---------------- kernel 2: softmax stats via QK recompute ------------------
// per CTA: 128 i-rows, stream 32 j-tiles; outputs (rowmax, 1/Z)
#define ST_OFF_K 18432
#define ST_OFF_S 36864
#define ST_SMEM  (36864 + 128 * LDSF * 4)   // 104448
__global__ __launch_bounds__(256) void stats_kernel(const __nv_bfloat16* __restrict__ Qb,
                                                    const __nv_bfloat16* __restrict__ Kb) {
    extern __shared__ char dyn[];
    __nv_bfloat16* Qs = (__nv_bfloat16*)(dyn);
    __nv_bfloat16* Ks = (__nv_bfloat16*)(dyn + ST_OFF_K);
    float*         Ss = (float*)(dyn + ST_OFF_S);
    const int tid = threadIdx.x, w = tid >> 5;
    const int b = blockIdx.y;
    const int i0 = blockIdx.x * 128;
    const uint32_t sQ = smem_u32(Qs);
    const uint32_t sK = smem_u32(Ks);

    // Q tile (persistent)
    const __nv_bfloat16* gQ = Qb + ((size_t)b * NPIX + i0) * CKDIM;
    #pragma unroll
    for (int p = 0; p < 4; ++p) {
        int idx = tid + p * 256;
        int row = idx >> 3, c8 = idx & 7;
        cpa16(sQ + row * (LDQ * 2) + c8 * 16, gQ + (size_t)row * CKDIM + c8 * 8);
    }
    cpa_commit();

    const int wm = w >> 1, wn = w & 1;
    const int row = tid >> 1, half = tid & 1;
    float mr = -3.0e38f, Zr = 0.f;

    for (int jt = 0; jt < 32; ++jt) {
        const __nv_bfloat16* gK = Kb + ((size_t)b * NPIX + jt * 128) * CKDIM;
        #pragma unroll
        for (int p = 0; p < 4; ++p) {
            int idx = tid + p * 256;
            int r = idx >> 3, c8 = idx & 7;
            cpa16(sK + r * (LDQ * 2) + c8 * 16, gK + (size_t)r * CKDIM + c8 * 8);
        }
        cpa_commit();
        cpa_wait<0>();
        __syncthreads();

        #pragma unroll
        for (int mi = 0; mi < 2; ++mi) {
            #pragma unroll
            for (int nj = 0; nj < 4; ++nj) {
                wmma::fragment<wmma::accumulator, 16, 16, 16, float> af_acc;
                wmma::fill_fragment(af_acc, 0.0f);
                #pragma unroll
                for (int kk = 0; kk < 64; kk += 16) {
                    wmma::fragment<wmma::matrix_a, 16, 16, 16, __nv_bfloat16, wmma::row_major> af;
                    wmma::fragment<wmma::matrix_b, 16, 16, 16, __nv_bfloat16, wmma::col_major> bf;
                    wmma::load_matrix_sync(af, Qs + (wm * 32 + mi * 16) * LDQ + kk, LDQ);
                    wmma::load_matrix_sync(bf, Ks + (wn * 64 + nj * 16) * LDQ + kk, LDQ);
                    wmma::mma_sync(af_acc, af, bf, af_acc);
                }
                wmma::store_matrix_sync(Ss + (wm * 32 + mi * 16) * LDSF + wn * 64 + nj * 16,
                                        af_acc, LDSF, wmma::mem_row_major);
            }
        }
        __syncthreads();

        // online softmax reduce: 2 threads per row, 64 cols each
        const float* sp = Ss + row * LDSF + half * 64;
        float lm = -3.0e38f;
        #pragma unroll
        for (int c = 0; c < 64; ++c) lm = fmaxf(lm, sp[c]);
        lm = fmaxf(lm, __shfl_xor_sync(0xffffffffu, lm, 1));
        float mnew = fmaxf(mr, lm);
        float s = 0.f;
        #pragma unroll
        for (int c = 0; c < 64; ++c) s += __expf(sp[c] - mnew);
        s += __shfl_xor_sync(0xffffffffu, s, 1);
        Zr = Zr * __expf(mr - mnew) + s;
        mr = mnew;
        __syncthreads();
    }

    if (half == 0)
        g_stats[(size_t)b * NPIX + i0 + row] = make_float2(mr, 1.0f / Zr);
}

// ---------------- kernel 3: fused QK -> softmax -> q -> PV -> epilogue ------
// out[b,c,m] = x[b,c,m] + base[b,c] - alpha * sum_n q[m,n] * V[c,n]
#define FU_OFF_K  18432
#define FU_OFF_V  36864
#define FU_OFF_QS 106496
#define FU_OFF_S  141312
#define FU_SMEM   (141312 + 128 * LDSF * 4)   // 208896
__global__ __launch_bounds__(256) void fused_kernel(const __nv_bfloat16* __restrict__ Qb,
                                                    const __nv_bfloat16* __restrict__ Kb,
                                                    const __nv_bfloat16* __restrict__ VH,
                                                    const float* __restrict__ xres,
                                                    const float* __restrict__ alpha,
                                                    float* __restrict__ out) {
    extern __shared__ char dyn[];
    __nv_bfloat16* Qs = (__nv_bfloat16*)(dyn);
    __nv_bfloat16* Ks = (__nv_bfloat16*)(dyn + FU_OFF_K);
    __nv_bfloat16* Vs = (__nv_bfloat16*)(dyn + FU_OFF_V);
    __nv_bfloat16* qs = (__nv_bfloat16*)(dyn + FU_OFF_QS);
    float*         Ss = (float*)(dyn + FU_OFF_S);
    __shared__ __align__(8) float2 s_stat[128];

    const int tid = threadIdx.x, w = tid >> 5;
    const int b  = blockIdx.y;
    const int m0 = blockIdx.x * 128;
    const uint32_t sQ = smem_u32(Qs);
    const uint32_t sK = smem_u32(Ks);
    const uint32_t sV = smem_u32(Vs);

    if (tid < 128) s_stat[tid] = g_stats[(size_t)b * NPIX + m0 + tid];

    // Q tile (persistent)
    const __nv_bfloat16* gQ = Qb + ((size_t)b * NPIX + m0) * CKDIM;
    #pragma unroll
    for (int p = 0; p < 4; ++p) {
        int idx = tid + p * 256;
        int row = idx >> 3, c8 = idx & 7;
        cpa16(sQ + row * (LDQ * 2) + c8 * 16, gQ + (size_t)row * CKDIM + c8 * 8);
    }
    cpa_commit();

    const int wm = w >> 1, wc = w & 1;
    const int row = tid >> 1, half = tid & 1;

    wmma::fragment<wmma::accumulator, 16, 16, 16, float> acc[2][8];
    #pragma unroll
    for (int mi = 0; mi < 2; ++mi)
        #pragma unroll
        for (int nj = 0; nj < 8; ++nj) wmma::fill_fragment(acc[mi][nj], 0.0f);

    for (int jt = 0; jt < 32; ++jt) {
        const int n0 = jt * 128;
        // K tile: 128 n-rows x 64
        const __nv_bfloat16* gK = Kb + ((size_t)b * NPIX + n0) * CKDIM;
        #pragma unroll
        for (int p = 0; p < 4; ++p) {
            int idx = tid + p * 256;
            int r = idx >> 3, c8 = idx & 7;
            cpa16(sK + r * (LDQ * 2) + c8 * 16, gK + (size_t)r * CKDIM + c8 * 8);
        }
        // V tile: 256 c-rows x 128 n
        const __nv_bfloat16* gV = VH + (size_t)b * CH * NPIX + n0;
        #pragma unroll
        for (int p = 0; p < 16; ++p) {
            int idx = tid + p * 256;
            int crow = idx >> 4, c16 = idx & 15;
            cpa16(sV + crow * (LDV * 2) + c16 * 16, gV + (size_t)crow * NPIX + c16 * 8);
        }
        cpa_commit();
        cpa_wait<0>();
        __syncthreads();

        // QK -> Ss
        #pragma unroll
        for (int mi = 0; mi < 2; ++mi) {
            #pragma unroll
            for (int nj = 0; nj < 4; ++nj) {
                wmma::fragment<wmma::accumulator, 16, 16, 16, float> sacc;
                wmma::fill_fragment(sacc, 0.0f);
                #pragma unroll
                for (int kk = 0; kk < 64; kk += 16) {
                    wmma::fragment<wmma::matrix_a, 16, 16, 16, __nv_bfloat16, wmma::row_major> af;
                    wmma::fragment<wmma::matrix_b, 16, 16, 16, __nv_bfloat16, wmma::col_major> bf;
                    wmma::load_matrix_sync(af, Qs + (wm * 32 + mi * 16) * LDQ + kk, LDQ);
                    wmma::load_matrix_sync(bf, Ks + (wc * 64 + nj * 16) * LDQ + kk, LDQ);
                    wmma::mma_sync(sacc, af, bf, sacc);
                }
                wmma::store_matrix_sync(Ss + (wm * 32 + mi * 16) * LDSF + wc * 64 + nj * 16,
                                        sacc, LDSF, wmma::mem_row_major);
            }
        }
        __syncthreads();

        // transform: p = exp(s - m)/Z ; q = 0.5*tanh(p/2) -> qs bf16
        {
            const float2 st = s_stat[row];
            const float* sp = Ss + row * LDSF + half * 64;
            __nv_bfloat16* qp = qs + row * LDV + half * 64;
            #pragma unroll
            for (int c = 0; c < 64; ++c) {
                float p = __expf(sp[c] - st.x) * st.y;
                qp[c] = __float2bfloat16(0.5f * tanhf(0.5f * p));
            }
        }
        __syncthreads();

        // PV accumulate: acc += q[128m x 128k] * V[128k x 256c]
        #pragma unroll
        for (int kk = 0; kk < 128; kk += 16) {
            wmma::fragment<wmma::matrix_a, 16, 16, 16, __nv_bfloat16, wmma::row_major> af[2];
            wmma::load_matrix_sync(af[0], qs + (wm * 32 +  0) * LDV + kk, LDV);
            wmma::load_matrix_sync(af[1], qs + (wm * 32 + 16) * LDV + kk, LDV);
            #pragma unroll
            for (int nj = 0; nj < 8; ++nj) {
                wmma::fragment<wmma::matrix_b, 16, 16, 16, __nv_bfloat16, wmma::col_major> bf;
                wmma::load_matrix_sync(bf, Vs + (wc * 128 + nj * 16) * LDV + kk, LDV);
                wmma::mma_sync(acc[0][nj], af[0], bf, acc[0][nj]);
                wmma::mma_sync(acc[1][nj], af[1], bf, acc[1][nj]);
            }
        }
        __syncthreads();   // protect Ks/Vs/qs before next iteration's loads
    }

    // epilogue: out = x + base[c] - alpha*acc, staged via Ss for exact fp32 base
    const float al = alpha[0];
    #pragma unroll
    for (int hc = 0; hc < 2; ++hc) {
        if (wc == hc) {
            #pragma unroll
            for (int mi = 0; mi < 2; ++mi)
                #pragma unroll
                for (int nj = 0; nj < 8; ++nj)
                    wmma::store_matrix_sync(Ss + (wm * 32 + mi * 16) * LDSF + nj * 16,
                                            acc[mi][nj], LDSF, wmma::mem_row_major);
        }
        __syncthreads();
        const int ml = tid & 127;
        const int chs = tid >> 7;    // 0..1
        #pragma unroll 4
        for (int c2 = 0; c2 < 64; ++c2) {
            int cl = c2 * 2 + chs;
            int c  = hc * 128 + cl;
            size_t o = ((size_t)b * CH + c) * NPIX + m0 + ml;
            out[o] = xres[o] + g_base[b * CH + c] - al * Ss[ml * LDSF + cl];
        }
        __syncthreads();
    }
}

// ---------------- launch ----------------
extern "C" void kernel_launch(void* const* d_in, const int* in_sizes, int n_in,
                              void* d_out, int out_size) {
    const float* x1    = (const float*)d_in[0];
    const float* x2    = (const float*)d_in[1];
    const float* x     = (const float*)d_in[2];
    const float* gamma = (const float*)d_in[3];
    const float* beta  = (const float*)d_in[4];
    const float* mean  = (const float*)d_in[5];
    const float* var   = (const float*)d_in[6];
    const float* Wb    = (const float*)d_in[7];
    const float* bb    = (const float*)d_in[8];
    const float* Wc    = (const float*)d_in[9];
    const float* bc    = (const float*)d_in[10];
    const float* Wd    = (const float*)d_in[11];
    const float* bd    = (const float*)d_in[12];
    const float* alpha = (const float*)d_in[13];
    float* out = (float*)d_out;

    __nv_bfloat16 *Qp, *Kp, *VHp;
    cudaGetSymbolAddress((void**)&Qp,  g_Qb);
    cudaGetSymbolAddress((void**)&Kp,  g_Kb);
    cudaGetSymbolAddress((void**)&VHp, g_VH);

    cudaFuncSetAttribute(stats_kernel, cudaFuncAttributeMaxDynamicSharedMemorySize, ST_SMEM);
    cudaFuncSetAttribute(fused_kernel, cudaFuncAttributeMaxDynamicSharedMemorySize, FU_SMEM);

    prep_kernel<<<1, 256>>>(gamma, beta, mean, var);
    colsum_kernel<<<dim3(CH, BATCH), 256>>>(x);
    sumv_kernel<<<BATCH, CH>>>(Wd, bd, alpha);

    projqk_kernel<<<dim3(NPIX / 64, 1, BATCH), 256>>>(x1, Wb, bb, Qp);
    projqk_kernel<<<dim3(NPIX / 64, 1, BATCH), 256>>>(x2, Wc, bc, Kp);
    projv_kernel <<<dim3(NPIX / 64, BATCH), 256>>>(x, Wd, bd, VHp);

    stats_kernel<<<dim3(NPIX / 128, BATCH), 256, ST_SMEM>>>(Qp, Kp);

    fused_kernel<<<dim3(NPIX / 128, BATCH), 256, FU_SMEM>>>(Qp, Kp, VHp, x, alpha, out);
}

// round 7
// speedup vs baseline: 1.5447x; 1.5447x over previous
#include <cuda_runtime.h>
#include <cuda_bf16.h>
#include <cuda_fp16.h>
#include <mma.h>
#include <math.h>
#include <stdint.h>

using namespace nvcuda;

#define BATCH 4
#define CH    256
#define CKDIM 64
#define NPIX  4096
#define EPS   1e-5f
#define LDT   72            // bf16 smem tile leading dim

#define DINL __device__ __forceinline__

// ---------------- device scratch (static, allocation-free) ----------------
__device__ __align__(16) float g_scale[CH];
__device__ __align__(16) float g_shift[CH];
__device__ __align__(16) float g_sx  [BATCH * CH];
__device__ __align__(16) float g_base[BATCH * CH];                        // alpha*0.5*SumV
__device__ __align__(16) __nv_bfloat16 g_Qb[BATCH * NPIX * CKDIM];        // [b][i][64]
__device__ __align__(16) __nv_bfloat16 g_Kb[BATCH * NPIX * CKDIM];        // [b][j][64]
__device__ __align__(16) __nv_bfloat16 g_VH[(size_t)BATCH * CH * NPIX];   // [b][c][n]
__device__ __align__(16) __half        g_S [(size_t)BATCH * NPIX * NPIX]; // fp16 scores
__device__ __align__(16) __nv_bfloat16 g_Aq[(size_t)BATCH * NPIX * NPIX]; // q = sig(p)-0.5

// ---------------- portable async-copy helpers (sm_80+ PTX) -----------------
DINL uint32_t smem_u32(const void* p) {
    uint32_t a;
    asm("{ .reg .u64 t; cvta.to.shared.u64 t, %1; cvt.u32.u64 %0, t; }"
        : "=r"(a) : "l"(p));
    return a;
}
DINL void cpa16(uint32_t dst, const void* src) {
    asm volatile("cp.async.cg.shared.global [%0], [%1], 16;"
                 :: "r"(dst), "l"(src) : "memory");
}
DINL void cpa_commit() { asm volatile("cp.async.commit_group;" ::: "memory"); }
template<int N> DINL void cpa_wait() {
    asm volatile("cp.async.wait_group %0;" :: "n"(N) : "memory");
}

// ---------------- kernel 0: fold BN ----------------
__global__ void prep_kernel(const float* __restrict__ gamma,
                            const float* __restrict__ beta,
                            const float* __restrict__ mean,
                            const float* __restrict__ var) {
    int c = threadIdx.x;
    if (c < CH) {
        float s = gamma[c] * rsqrtf(var[c] + EPS);
        g_scale[c] = s;
        g_shift[c] = beta[c] - mean[c] * s;
    }
}

// ---------------- kernel 0b: column sums of x -> sx[b][c] -------------------
__global__ void colsum_kernel(const float* __restrict__ x) {
    const int c = blockIdx.x, b = blockIdx.y;
    const float* row = x + ((size_t)b * CH + c) * NPIX;
    const int t = threadIdx.x;
    float s = 0.f;
    #pragma unroll
    for (int q = 0; q < 16; ++q) s += row[t + q * 256];
    #pragma unroll
    for (int o = 16; o; o >>= 1) s += __shfl_xor_sync(0xffffffffu, s, o);
    __shared__ float ws[8];
    if ((t & 31) == 0) ws[t >> 5] = s;
    __syncthreads();
    if (t == 0) {
        float tot = 0.f;
        #pragma unroll
        for (int w = 0; w < 8; ++w) tot += ws[w];
        g_sx[b * CH + c] = tot;
    }
}

// ---------------- kernel 0c: base[b][c] = alpha*0.5*(Wd[c,:]·sx[b,:] + N*bd) -
__global__ void sumv_kernel(const float* __restrict__ Wd,
                            const float* __restrict__ bd,
                            const float* __restrict__ alpha) {
    const int b = blockIdx.x;
    const int c = threadIdx.x;
    __shared__ float sxs[CH];
    sxs[c] = g_sx[b * CH + c];
    __syncthreads();
    float dot = 0.f;
    const float* wr = Wd + (size_t)c * CH;
    #pragma unroll 8
    for (int k = 0; k < CH; ++k) dot += wr[k] * sxs[k];
    g_base[b * CH + c] = alpha[0] * 0.5f * (dot + (float)NPIX * bd[c]);
}

// ---------------- kernel 1a: merged Q & K projections (BN folded) -----------
// grid (NPIX/64, 2, BATCH); y=0 -> Q from x1/Wb/bb, y=1 -> K from x2/Wc/bc
__global__ void projqk_kernel(const float* __restrict__ x1,
                              const float* __restrict__ x2,
                              const float* __restrict__ Wb,
                              const float* __restrict__ bb,
                              const float* __restrict__ Wc,
                              const float* __restrict__ bc,
                              __nv_bfloat16* __restrict__ Qo,
                              __nv_bfloat16* __restrict__ Ko) {
    __shared__ float As[16][65];
    __shared__ float Bs[16][65];
    const int which = blockIdx.y;
    const float* x   = which ? x2 : x1;
    const float* W   = which ? Wc : Wb;
    const float* bias= which ? bc : bb;
    __nv_bfloat16* out = which ? Ko : Qo;

    const int b  = blockIdx.z;
    const int n0 = blockIdx.x * 64;
    const float* xb = x + (size_t)b * CH * NPIX;
    const int tid = threadIdx.x;
    const int tk = tid & 15;
    const int tn = tid >> 4;

    float acc[4][4] = {};
    for (int c0 = 0; c0 < CH; c0 += 16) {
        {
            int nn = tid & 63, cb = tid >> 6;
            #pragma unroll
            for (int r = 0; r < 4; ++r) {
                int cc = cb + r * 4;
                float v = xb[(size_t)(c0 + cc) * NPIX + n0 + nn];
                As[cc][nn] = v * g_scale[c0 + cc] + g_shift[c0 + cc];
            }
        }
        {
            int cc = tid & 15, kb = tid >> 4;
            #pragma unroll
            for (int r = 0; r < 4; ++r) {
                int kk = kb + r * 16;
                Bs[cc][kk] = W[(size_t)kk * CH + c0 + cc];
            }
        }
        __syncthreads();
        #pragma unroll
        for (int cc = 0; cc < 16; ++cc) {
            float a[4], bv[4];
            #pragma unroll
            for (int i = 0; i < 4; ++i) a[i]  = As[cc][tn + i * 16];
            #pragma unroll
            for (int j = 0; j < 4; ++j) bv[j] = Bs[cc][tk + j * 16];
            #pragma unroll
            for (int i = 0; i < 4; ++i)
                #pragma unroll
                for (int j = 0; j < 4; ++j) acc[i][j] += a[i] * bv[j];
        }
        __syncthreads();
    }
    __nv_bfloat16* ob = out + (size_t)b * NPIX * CKDIM;
    #pragma unroll
    for (int i = 0; i < 4; ++i) {
        int n = n0 + tn + i * 16;
        #pragma unroll
        for (int j = 0; j < 4; ++j) {
            int k = tk + j * 16;
            ob[(size_t)n * CKDIM + k] = __float2bfloat16(acc[i][j] + bias[k]);
        }
    }
}

// ---------------- kernel 1b: V projection, bf16 [b][d][n], x read ONCE ------
__global__ __launch_bounds__(256) void projv_kernel(const float* __restrict__ x,
                                                    const float* __restrict__ W,
                                                    const float* __restrict__ bias,
                                                    __nv_bfloat16* __restrict__ vh) {
    __shared__ float As[16][65];    // c x n
    __shared__ float Bs[16][264];   // c x d
    const int b  = blockIdx.y;
    const int n0 = blockIdx.x * 64;
    const float* xb = x + (size_t)b * CH * NPIX;
    const int tid = threadIdx.x;
    const int tn = tid & 15;
    const int td = tid >> 4;

    float acc[16][4] = {};
    for (int c0 = 0; c0 < CH; c0 += 16) {
        {
            int nn = tid & 63, cb = tid >> 6;
            #pragma unroll
            for (int r = 0; r < 4; ++r) {
                int cc = cb + r * 4;
                As[cc][nn] = xb[(size_t)(c0 + cc) * NPIX + n0 + nn];
            }
        }
        {
            int cc = tid & 15, db = tid >> 4;
            #pragma unroll
            for (int r = 0; r < 16; ++r) {
                int dd = db + r * 16;
                Bs[cc][dd] = W[(size_t)dd * CH + c0 + cc];
            }
        }
        __syncthreads();
        #pragma unroll
        for (int cc = 0; cc < 16; ++cc) {
            float a[4], w[16];
            #pragma unroll
            for (int j = 0; j < 4; ++j) a[j] = As[cc][tn + j * 16];
            #pragma unroll
            for (int i = 0; i < 16; ++i) w[i] = Bs[cc][td + i * 16];
            #pragma unroll
            for (int i = 0; i < 16; ++i)
                #pragma unroll
                for (int j = 0; j < 4; ++j) acc[i][j] += w[i] * a[j];
        }
        __syncthreads();
    }
    #pragma unroll
    for (int i = 0; i < 16; ++i) {
        int d = td + i * 16;
        float bd_ = bias[d];
        #pragma unroll
        for (int j = 0; j < 4; ++j) {
            int n = n0 + tn + j * 16;
            vh[((size_t)b * CH + d) * NPIX + n] = __float2bfloat16(acc[i][j] + bd_);
        }
    }
}

// ---------------- kernel 2: scores = Q @ K^T via wmma bf16 -> fp16 S --------
// CTA 128i x 128j, 8 warps (wm 0..3 x wc 0..1), warp tile 32i x 64j
// dyn smem: Qs 18432 | Ks 18432 | per-warp scratch 16x68 fp32 (8 x 4352)
#define QK_OFF_K   18432
#define QK_OFF_SCR 36864
#define QK_SMEM    (36864 + 8 * 16 * 68 * 4)   // 71680
__global__ __launch_bounds__(256) void qk_wmma_kernel(const __nv_bfloat16* __restrict__ Qb,
                                                      const __nv_bfloat16* __restrict__ Kb,
                                                      __half* __restrict__ S) {
    extern __shared__ char dyn[];
    __nv_bfloat16* Qs = (__nv_bfloat16*)(dyn);
    __nv_bfloat16* Ks = (__nv_bfloat16*)(dyn + QK_OFF_K);
    const int tid = threadIdx.x, w = tid >> 5, lane = tid & 31;
    float* scr = (float*)(dyn + QK_OFF_SCR) + w * (16 * 68);

    const int b  = blockIdx.z;
    const int i0 = blockIdx.y * 128;
    const int j0 = blockIdx.x * 128;

    const uint4* gQ = (const uint4*)(Qb + ((size_t)b * NPIX + i0) * CKDIM);
    const uint4* gK = (const uint4*)(Kb + ((size_t)b * NPIX + j0) * CKDIM);
    #pragma unroll
    for (int p = 0; p < 4; ++p) {
        int idx = tid + p * 256;
        int row = idx >> 3, c8 = idx & 7;
        *(uint4*)&Qs[row * LDT + c8 * 8] = gQ[idx];
        *(uint4*)&Ks[row * LDT + c8 * 8] = gK[idx];
    }
    __syncthreads();

    const int wm = w >> 1, wc = w & 1;
    wmma::fragment<wmma::accumulator, 16, 16, 16, float> acc[2][4];
    #pragma unroll
    for (int mi = 0; mi < 2; ++mi)
        #pragma unroll
        for (int nj = 0; nj < 4; ++nj) wmma::fill_fragment(acc[mi][nj], 0.0f);

    #pragma unroll
    for (int kk = 0; kk < 64; kk += 16) {
        wmma::fragment<wmma::matrix_a, 16, 16, 16, __nv_bfloat16, wmma::row_major> af[2];
        wmma::load_matrix_sync(af[0], Qs + (wm * 32 +  0) * LDT + kk, LDT);
        wmma::load_matrix_sync(af[1], Qs + (wm * 32 + 16) * LDT + kk, LDT);
        #pragma unroll
        for (int nj = 0; nj < 4; ++nj) {
            wmma::fragment<wmma::matrix_b, 16, 16, 16, __nv_bfloat16, wmma::col_major> bf;
            wmma::load_matrix_sync(bf, Ks + (wc * 64 + nj * 16) * LDT + kk, LDT);
            wmma::mma_sync(acc[0][nj], af[0], bf, acc[0][nj]);
            wmma::mma_sync(acc[1][nj], af[1], bf, acc[1][nj]);
        }
    }

    // stage fp32 -> fp16, emit coalesced 128B rows
    #pragma unroll
    for (int mi = 0; mi < 2; ++mi) {
        #pragma unroll
        for (int nj = 0; nj < 4; ++nj)
            wmma::store_matrix_sync(scr + nj * 16, acc[mi][nj], 68, wmma::mem_row_major);
        __syncwarp();
        const int irow = i0 + wm * 32 + mi * 16;
        uint32_t* outp = (uint32_t*)(S + ((size_t)b * NPIX + irow) * NPIX + j0 + wc * 64);
        #pragma unroll
        for (int r = 0; r < 16; ++r) {
            float2 v = *(float2*)&scr[r * 68 + lane * 2];
            __half2 h2 = __float22half2_rn(v);
            outp[(size_t)r * (NPIX / 2) + lane] = *(uint32_t*)&h2;
        }
        __syncwarp();
    }
}

// ---------------- kernel 3: softmax row -> q = 0.5*tanh(p/2) bf16 -----------
__global__ void att_kernel(const __half* __restrict__ S,
                           __nv_bfloat16* __restrict__ Aq) {
    const size_t roff = ((size_t)blockIdx.y * NPIX + blockIdx.x) * (size_t)NPIX;
    const __half* r = S + roff;
    const int t = threadIdx.x;
    const int lane = t & 31, wid = t >> 5;
    __shared__ float smax[8];
    __shared__ float ssum[8];

    float v[16];
    float mx = -1e30f;
    #pragma unroll
    for (int q = 0; q < 16; ++q) { v[q] = __half2float(r[t + q * 256]); mx = fmaxf(mx, v[q]); }
    #pragma unroll
    for (int o = 16; o; o >>= 1) mx = fmaxf(mx, __shfl_xor_sync(0xffffffffu, mx, o));
    if (lane == 0) smax[wid] = mx;
    __syncthreads();
    mx = smax[0];
    #pragma unroll
    for (int w = 1; w < 8; ++w) mx = fmaxf(mx, smax[w]);

    float s = 0.f;
    #pragma unroll
    for (int q = 0; q < 16; ++q) { v[q] = __expf(v[q] - mx); s += v[q]; }
    #pragma unroll
    for (int o = 16; o; o >>= 1) s += __shfl_xor_sync(0xffffffffu, s, o);
    if (lane == 0) ssum[wid] = s;
    __syncthreads();
    float Z = 0.f;
    #pragma unroll
    for (int w = 0; w < 8; ++w) Z += ssum[w];
    float inv = 1.0f / Z;

    #pragma unroll
    for (int q = 0; q < 16; ++q) {
        float p = v[q] * inv;
        float qq = 0.5f * tanhf(0.5f * p);        // sigmoid(p) - 0.5
        Aq[roff + t + q * 256] = __float2bfloat16(qq);
    }
}

// ---------------- kernel 4: out[b,c,m] = x + base[c] - alpha * sum_n q*V ----
// bf16 GEMM: CTA 128m x 256c, 8 warps, K=4096 in 64-chunks, 3 cp.async stages
#define PV_STAGE_B ((128 * LDT + 256 * LDT) * 2)   // 55296 bytes per stage
#define PV_SMEM    (3 * PV_STAGE_B + 256)          // 166144
#define LDE 260
__global__ __launch_bounds__(256) void pv_wmma_kernel(const __nv_bfloat16* __restrict__ Aq,
                                                      const __nv_bfloat16* __restrict__ VH,
                                                      const float* __restrict__ xres,
                                                      const float* __restrict__ alpha,
                                                      float* __restrict__ out) {
    extern __shared__ char dyn[];
    const int tid = threadIdx.x, w = tid >> 5;
    const int b  = blockIdx.y;
    const int m0 = blockIdx.x * 128;

    uint32_t dynb = smem_u32(dyn);
    uint32_t base = (dynb + 255u) & ~255u;
    char* sb = dyn + (base - dynb);
    const uint32_t sbase = base;

    const __nv_bfloat16* pa = Aq + ((size_t)b * NPIX + m0) * (size_t)NPIX;
    const __nv_bfloat16* pb = VH + (size_t)b * CH * NPIX;

    auto issue_stage = [&](int t) {
        const int s = t % 3;
        const uint32_t dA = sbase + (uint32_t)s * PV_STAGE_B;
        const uint32_t dB = dA + 128 * LDT * 2;
        const int n0 = t << 6;
        #pragma unroll
        for (int p = 0; p < 4; ++p) {           // A: 128 rows x 64 bf16
            int idx = tid + p * 256;
            int row = idx >> 3, c8 = idx & 7;
            cpa16(dA + (uint32_t)(row * LDT + c8 * 8) * 2,
                  pa + (size_t)row * NPIX + n0 + c8 * 8);
        }
        #pragma unroll
        for (int p = 0; p < 8; ++p) {           // B: 256 rows x 64 bf16
            int idx = tid + p * 256;
            int row = idx >> 3, c8 = idx & 7;
            cpa16(dB + (uint32_t)(row * LDT + c8 * 8) * 2,
                  pb + (size_t)row * NPIX + n0 + c8 * 8);
        }
        cpa_commit();
    };

    const int wm = w >> 1, wc = w & 1;
    wmma::fragment<wmma::accumulator, 16, 16, 16, float> acc[2][8];
    #pragma unroll
    for (int mi = 0; mi < 2; ++mi)
        #pragma unroll
        for (int nj = 0; nj < 8; ++nj) wmma::fill_fragment(acc[mi][nj], 0.0f);

    issue_stage(0);
    issue_stage(1);

    for (int t = 0; t < 64; ++t) {
        if (t < 63) cpa_wait<1>(); else cpa_wait<0>();
        __syncthreads();

        const __nv_bfloat16* cA = (const __nv_bfloat16*)(sb + (size_t)(t % 3) * PV_STAGE_B);
        const __nv_bfloat16* cB = cA + 128 * LDT;
        #pragma unroll
        for (int kk = 0; kk < 64; kk += 16) {
            wmma::fragment<wmma::matrix_a, 16, 16, 16, __nv_bfloat16, wmma::row_major> af[2];
            wmma::load_matrix_sync(af[0], cA + (wm * 32 +  0) * LDT + kk, LDT);
            wmma::load_matrix_sync(af[1], cA + (wm * 32 + 16) * LDT + kk, LDT);
            #pragma unroll
            for (int nj = 0; nj < 8; ++nj) {
                wmma::fragment<wmma::matrix_b, 16, 16, 16, __nv_bfloat16, wmma::col_major> bf;
                wmma::load_matrix_sync(bf, cB + (wc * 128 + nj * 16) * LDT + kk, LDT);
                wmma::mma_sync(acc[0][nj], af[0], bf, acc[0][nj]);
                wmma::mma_sync(acc[1][nj], af[1], bf, acc[1][nj]);
            }
        }

        if (t + 2 < 64) issue_stage(t + 2);
    }

    // epilogue: stage full 128m x 256c acc in smem, then
    //   out = x + base[c] - alpha*acc  (coalesced in m)
    __syncthreads();
    float* Sep = (float*)sb;                     // 128 * LDE * 4 = 133,120 B
    #pragma unroll
    for (int mi = 0; mi < 2; ++mi)
        #pragma unroll
        for (int nj = 0; nj < 8; ++nj)
            wmma::store_matrix_sync(Sep + (wm * 32 + mi * 16) * LDE + wc * 128 + nj * 16,
                                    acc[mi][nj], LDE, wmma::mem_row_major);
    __syncthreads();

    const float al = alpha[0];
    const int ml = tid & 127;
    const int ch = tid >> 7;                     // 0..1
    #pragma unroll 4
    for (int c2 = 0; c2 < 128; ++c2) {
        int c = ch * 128 + c2;
        size_t o = ((size_t)b * CH + c) * NPIX + m0 + ml;
        out[o] = xres[o] + g_base[b * CH + c] - al * Sep[ml * LDE + c];
    }
}

// ---------------- launch ----------------
extern "C" void kernel_launch(void* const* d_in, const int* in_sizes, int n_in,
                              void* d_out, int out_size) {
    const float* x1    = (const float*)d_in[0];
    const float* x2    = (const float*)d_in[1];
    const float* x     = (const float*)d_in[2];
    const float* gamma = (const float*)d_in[3];
    const float* beta  = (const float*)d_in[4];
    const float* mean  = (const float*)d_in[5];
    const float* var   = (const float*)d_in[6];
    const float* Wb    = (const float*)d_in[7];
    const float* bb    = (const float*)d_in[8];
    const float* Wc    = (const float*)d_in[9];
    const float* bc    = (const float*)d_in[10];
    const float* Wd    = (const float*)d_in[11];
    const float* bd    = (const float*)d_in[12];
    const float* alpha = (const float*)d_in[13];
    float* out = (float*)d_out;

    __nv_bfloat16 *Qp, *Kp, *VHp, *Aqp;
    __half* Sp;
    cudaGetSymbolAddress((void**)&Qp,  g_Qb);
    cudaGetSymbolAddress((void**)&Kp,  g_Kb);
    cudaGetSymbolAddress((void**)&VHp, g_VH);
    cudaGetSymbolAddress((void**)&Sp,  g_S);
    cudaGetSymbolAddress((void**)&Aqp, g_Aq);

    cudaFuncSetAttribute(qk_wmma_kernel, cudaFuncAttributeMaxDynamicSharedMemorySize, QK_SMEM);
    cudaFuncSetAttribute(pv_wmma_kernel, cudaFuncAttributeMaxDynamicSharedMemorySize, PV_SMEM);

    prep_kernel<<<1, 256>>>(gamma, beta, mean, var);
    colsum_kernel<<<dim3(CH, BATCH), 256>>>(x);
    sumv_kernel<<<BATCH, CH>>>(Wd, bd, alpha);

    projqk_kernel<<<dim3(NPIX / 64, 2, BATCH), 256>>>(x1, x2, Wb, bb, Wc, bc, Qp, Kp);
    projv_kernel <<<dim3(NPIX / 64, BATCH), 256>>>(x, Wd, bd, VHp);

    qk_wmma_kernel<<<dim3(NPIX / 128, NPIX / 128, BATCH), 256, QK_SMEM>>>(Qp, Kp, Sp);

    att_kernel<<<dim3(NPIX, BATCH), 256>>>(Sp, Aqp);

    pv_wmma_kernel<<<dim3(NPIX / 128, BATCH), 256, PV_SMEM>>>(Aqp, VHp, x, alpha, out);
}

// round 10
// speedup vs baseline: 1.9693x; 1.2749x over previous
#include <cuda_runtime.h>
#include <cuda_bf16.h>
#include <cuda_fp16.h>
#include <mma.h>
#include <math.h>
#include <stdint.h>

using namespace nvcuda;

#define BATCH 4
#define CH    256
#define CKDIM 64
#define NPIX  4096
#define EPS   1e-5f
#define LDT   72            // bf16 smem tile leading dim

#define DINL __device__ __forceinline__

// ---------------- device scratch (static, allocation-free) ----------------
__device__ __align__(16) float g_scale[CH];
__device__ __align__(16) float g_shift[CH];
__device__ __align__(16) float g_sx  [BATCH * CH];
__device__ __align__(16) float g_base[BATCH * CH];                        // alpha*0.5*SumV
__device__ __align__(16) float g_Wqt [CH * CKDIM];                        // BN-folded, [c][k]
__device__ __align__(16) float g_Wkt [CH * CKDIM];
__device__ __align__(16) float g_bq  [CKDIM];
__device__ __align__(16) float g_bk  [CKDIM];
__device__ __align__(16) float g_Wdt [CH * CH];                           // Wd^T, [c][d]
__device__ __align__(16) __nv_bfloat16 g_Qb[BATCH * NPIX * CKDIM];        // [b][i][64]
__device__ __align__(16) __nv_bfloat16 g_Kb[BATCH * NPIX * CKDIM];        // [b][j][64]
__device__ __align__(16) __nv_bfloat16 g_VH[(size_t)BATCH * CH * NPIX];   // [b][c][n]
__device__ __align__(16) __half        g_S [(size_t)BATCH * NPIX * NPIX]; // fp16 scores
__device__ __align__(16) __nv_bfloat16 g_Aq[(size_t)BATCH * NPIX * NPIX]; // q = sig(p)-0.5

// ---------------- streams/events (static init: no device mem alloc) --------
static cudaStream_t g_s2;
static cudaEvent_t  g_evF, g_evJ;
static struct _StrInit {
    _StrInit() {
        cudaStreamCreateWithFlags(&g_s2, cudaStreamNonBlocking);
        cudaEventCreateWithFlags(&g_evF, cudaEventDisableTiming);
        cudaEventCreateWithFlags(&g_evJ, cudaEventDisableTiming);
    }
} g_strInit;

// ---------------- helpers ----------------
DINL uint32_t smem_u32(const void* p) {
    uint32_t a;
    asm("{ .reg .u64 t; cvta.to.shared.u64 t, %1; cvt.u32.u64 %0, t; }"
        : "=r"(a) : "l"(p));
    return a;
}
DINL void cpa16(uint32_t dst, const void* src) {
    asm volatile("cp.async.cg.shared.global [%0], [%1], 16;"
                 :: "r"(dst), "l"(src) : "memory");
}
DINL void cpa_commit() { asm volatile("cp.async.commit_group;" ::: "memory"); }
template<int N> DINL void cpa_wait() {
    asm volatile("cp.async.wait_group %0;" :: "n"(N) : "memory");
}
DINL float tanh_fast(float x) {
    float y;
    asm("tanh.approx.f32 %0, %1;" : "=f"(y) : "f"(x));
    return y;
}

// ---------------- kernel 0: fold BN ----------------
__global__ void prep_kernel(const float* __restrict__ gamma,
                            const float* __restrict__ beta,
                            const float* __restrict__ mean,
                            const float* __restrict__ var) {
    int c = threadIdx.x;
    if (c < CH) {
        float s = gamma[c] * rsqrtf(var[c] + EPS);
        g_scale[c] = s;
        g_shift[c] = beta[c] - mean[c] * s;
    }
}

// ---------------- kernel 0a: fold BN into Wb/Wc, transpose -> [c][k] --------
// grid (CKDIM, 2), block 256
__global__ void foldw_kernel(const float* __restrict__ Wb,
                             const float* __restrict__ bb,
                             const float* __restrict__ Wc,
                             const float* __restrict__ bc) {
    const int k = blockIdx.x, which = blockIdx.y;
    const float* W  = which ? Wc : Wb;
    const float* bi = which ? bc : bb;
    float* Wt = which ? g_Wkt : g_Wqt;
    float* bo = which ? g_bk  : g_bq;
    const int c = threadIdx.x;
    float w = W[(size_t)k * CH + c];
    Wt[c * CKDIM + k] = w * g_scale[c];
    float sh = w * g_shift[c];
    #pragma unroll
    for (int o = 16; o; o >>= 1) sh += __shfl_xor_sync(0xffffffffu, sh, o);
    __shared__ float red[8];
    if ((c & 31) == 0) red[c >> 5] = sh;
    __syncthreads();
    if (c == 0) {
        float tot = 0.f;
        #pragma unroll
        for (int w8 = 0; w8 < 8; ++w8) tot += red[w8];
        bo[k] = bi[k] + tot;
    }
}

// ---------------- kernel 0e: transpose Wd -> [c][d] -------------------------
__global__ void transwd_kernel(const float* __restrict__ Wd) {
    const int d = blockIdx.x, c = threadIdx.x;
    g_Wdt[(size_t)c * CH + d] = Wd[(size_t)d * CH + c];
}

// ---------------- kernel 0b: column sums of x -> sx[b][c] -------------------
__global__ void colsum_kernel(const float* __restrict__ x) {
    const int c = blockIdx.x, b = blockIdx.y;
    const float* row = x + ((size_t)b * CH + c) * NPIX;
    const int t = threadIdx.x;
    float s = 0.f;
    #pragma unroll
    for (int q = 0; q < 16; ++q) s += row[t + q * 256];
    #pragma unroll
    for (int o = 16; o; o >>= 1) s += __shfl_xor_sync(0xffffffffu, s, o);
    __shared__ float ws[8];
    if ((t & 31) == 0) ws[t >> 5] = s;
    __syncthreads();
    if (t == 0) {
        float tot = 0.f;
        #pragma unroll
        for (int w = 0; w < 8; ++w) tot += ws[w];
        g_sx[b * CH + c] = tot;
    }
}

// ---------------- kernel 0c: base[b][c] = alpha*0.5*(Wd[c,:]·sx[b,:] + N*bd) -
__global__ void sumv_kernel(const float* __restrict__ Wd,
                            const float* __restrict__ bd,
                            const float* __restrict__ alpha) {
    const int b = blockIdx.x;
    const int c = threadIdx.x;
    __shared__ float sxs[CH];
    sxs[c] = g_sx[b * CH + c];
    __syncthreads();
    float dot = 0.f;
    const float* wr = Wd + (size_t)c * CH;
    #pragma unroll 8
    for (int k = 0; k < CH; ++k) dot += wr[k] * sxs[k];
    g_base[b * CH + c] = alpha[0] * 0.5f * (dot + (float)NPIX * bd[c]);
}

// ---------------- kernel 1a: Q & K projections (weights pre-folded) ---------
// grid (NPIX/64, 2, BATCH), 256 threads, float4 smem path
__global__ __launch_bounds__(256) void projqk_kernel(const float* __restrict__ x1,
                                                     const float* __restrict__ x2,
                                                     __nv_bfloat16* __restrict__ Qo,
                                                     __nv_bfloat16* __restrict__ Ko) {
    __shared__ float As[16][68];   // [c][n]
    __shared__ float Bs[16][68];   // [c][k]
    const int which = blockIdx.y;
    const float* x  = which ? x2 : x1;
    const float* Wt = which ? g_Wkt : g_Wqt;
    const float* bv = which ? g_bk : g_bq;
    __nv_bfloat16* out = which ? Ko : Qo;

    const int b  = blockIdx.z;
    const int n0 = blockIdx.x * 64;
    const float* xb = x + (size_t)b * CH * NPIX;
    const int tid = threadIdx.x;
    const int tk = tid & 15;       // k group (fast -> coalesced stores)
    const int tn = tid >> 4;       // n group

    float acc[4][4] = {};          // [i over n][j over k]
    for (int c0 = 0; c0 < CH; c0 += 16) {
        {
            int c16 = tid & 15, cc = tid >> 4;
            *(float4*)&As[cc][c16 * 4] =
                *(const float4*)&xb[(size_t)(c0 + cc) * NPIX + n0 + c16 * 4];
            *(float4*)&Bs[cc][c16 * 4] =
                *(const float4*)&Wt[(size_t)(c0 + cc) * CKDIM + c16 * 4];
        }
        __syncthreads();
        #pragma unroll
        for (int cc = 0; cc < 16; ++cc) {
            float4 a4 = *(float4*)&As[cc][tn * 4];
            float4 w4 = *(float4*)&Bs[cc][tk * 4];
            float av[4] = {a4.x, a4.y, a4.z, a4.w};
            float wv[4] = {w4.x, w4.y, w4.z, w4.w};
            #pragma unroll
            for (int i = 0; i < 4; ++i)
                #pragma unroll
                for (int j = 0; j < 4; ++j) acc[i][j] += av[i] * wv[j];
        }
        __syncthreads();
    }
    const float b0 = bv[tk * 4 + 0], b1 = bv[tk * 4 + 1];
    const float b2 = bv[tk * 4 + 2], b3 = bv[tk * 4 + 3];
    #pragma unroll
    for (int i = 0; i < 4; ++i) {
        int n = n0 + tn * 4 + i;
        __nv_bfloat162 lo = __floats2bfloat162_rn(acc[i][0] + b0, acc[i][1] + b1);
        __nv_bfloat162 hi = __floats2bfloat162_rn(acc[i][2] + b2, acc[i][3] + b3);
        uint2 u;
        u.x = *(uint32_t*)&lo;
        u.y = *(uint32_t*)&hi;
        *(uint2*)&out[((size_t)b * NPIX + n) * CKDIM + tk * 4] = u;
    }
}

// ---------------- kernel 1b: V projection (Wdt pre-transposed) --------------
// CTA: 64 n x 256 d, 256 threads; thread: 16 contiguous d x 4 contiguous n
__global__ __launch_bounds__(256) void projv_kernel(const float* __restrict__ x,
                                                    const float* __restrict__ bd,
                                                    __nv_bfloat16* __restrict__ vh) {
    __shared__ float As[16][68];    // [c][n]
    __shared__ float Bs[16][260];   // [c][d]
    const int b  = blockIdx.y;
    const int n0 = blockIdx.x * 64;
    const float* xb = x + (size_t)b * CH * NPIX;
    const int tid = threadIdx.x;
    const int tn = tid & 15;
    const int td = tid >> 4;

    float acc[16][4] = {};
    for (int c0 = 0; c0 < CH; c0 += 16) {
        {
            int c16 = tid & 15, cc = tid >> 4;
            *(float4*)&As[cc][c16 * 4] =
                *(const float4*)&xb[(size_t)(c0 + cc) * NPIX + n0 + c16 * 4];
        }
        #pragma unroll
        for (int r = 0; r < 4; ++r) {
            int idx = tid + r * 256;
            int cc = idx >> 6, d4 = (idx & 63) * 4;
            *(float4*)&Bs[cc][d4] = *(const float4*)&g_Wdt[(size_t)(c0 + cc) * CH + d4];
        }
        __syncthreads();
        #pragma unroll
        for (int cc = 0; cc < 16; ++cc) {
            float4 a4 = *(float4*)&As[cc][tn * 4];
            float av[4] = {a4.x, a4.y, a4.z, a4.w};
            float wv[16];
            #pragma unroll
            for (int g = 0; g < 4; ++g) {
                float4 w4 = *(float4*)&Bs[cc][td * 16 + g * 4];
                wv[g * 4 + 0] = w4.x; wv[g * 4 + 1] = w4.y;
                wv[g * 4 + 2] = w4.z; wv[g * 4 + 3] = w4.w;
            }
            #pragma unroll
            for (int i = 0; i < 16; ++i)
                #pragma unroll
                for (int j = 0; j < 4; ++j) acc[i][j] += wv[i] * av[j];
        }
        __syncthreads();
    }
    #pragma unroll
    for (int i = 0; i < 16; ++i) {
        int d = td * 16 + i;
        float bdv = bd[d];
        __nv_bfloat162 lo = __floats2bfloat162_rn(acc[i][0] + bdv, acc[i][1] + bdv);
        __nv_bfloat162 hi = __floats2bfloat162_rn(acc[i][2] + bdv, acc[i][3] + bdv);
        uint2 u;
        u.x = *(uint32_t*)&lo;
        u.y = *(uint32_t*)&hi;
        *(uint2*)&vh[((size_t)b * CH + d) * NPIX + n0 + tn * 4] = u;
    }
}

// ---------------- kernel 2: scores = Q @ K^T via wmma bf16 -> fp16 S --------
#define QK_OFF_K   18432
#define QK_OFF_SCR 36864
#define QK_SMEM    (36864 + 8 * 16 * 68 * 4)   // 71680
__global__ __launch_bounds__(256) void qk_wmma_kernel(const __nv_bfloat16* __restrict__ Qb,
                                                      const __nv_bfloat16* __restrict__ Kb,
                                                      __half* __restrict__ S) {
    extern __shared__ char dyn[];
    __nv_bfloat16* Qs = (__nv_bfloat16*)(dyn);
    __nv_bfloat16* Ks = (__nv_bfloat16*)(dyn + QK_OFF_K);
    const int tid = threadIdx.x, w = tid >> 5, lane = tid & 31;
    float* scr = (float*)(dyn + QK_OFF_SCR) + w * (16 * 68);

    const int b  = blockIdx.z;
    const int i0 = blockIdx.y * 128;
    const int j0 = blockIdx.x * 128;

    const uint4* gQ = (const uint4*)(Qb + ((size_t)b * NPIX + i0) * CKDIM);
    const uint4* gK = (const uint4*)(Kb + ((size_t)b * NPIX + j0) * CKDIM);
    #pragma unroll
    for (int p = 0; p < 4; ++p) {
        int idx = tid + p * 256;
        int row = idx >> 3, c8 = idx & 7;
        *(uint4*)&Qs[row * LDT + c8 * 8] = gQ[idx];
        *(uint4*)&Ks[row * LDT + c8 * 8] = gK[idx];
    }
    __syncthreads();

    const int wm = w >> 1, wc = w & 1;
    wmma::fragment<wmma::accumulator, 16, 16, 16, float> acc[2][4];
    #pragma unroll
    for (int mi = 0; mi < 2; ++mi)
        #pragma unroll
        for (int nj = 0; nj < 4; ++nj) wmma::fill_fragment(acc[mi][nj], 0.0f);

    #pragma unroll
    for (int kk = 0; kk < 64; kk += 16) {
        wmma::fragment<wmma::matrix_a, 16, 16, 16, __nv_bfloat16, wmma::row_major> af[2];
        wmma::load_matrix_sync(af[0], Qs + (wm * 32 +  0) * LDT + kk, LDT);
        wmma::load_matrix_sync(af[1], Qs + (wm * 32 + 16) * LDT + kk, LDT);
        #pragma unroll
        for (int nj = 0; nj < 4; ++nj) {
            wmma::fragment<wmma::matrix_b, 16, 16, 16, __nv_bfloat16, wmma::col_major> bf;
            wmma::load_matrix_sync(bf, Ks + (wc * 64 + nj * 16) * LDT + kk, LDT);
            wmma::mma_sync(acc[0][nj], af[0], bf, acc[0][nj]);
            wmma::mma_sync(acc[1][nj], af[1], bf, acc[1][nj]);
        }
    }

    #pragma unroll
    for (int mi = 0; mi < 2; ++mi) {
        #pragma unroll
        for (int nj = 0; nj < 4; ++nj)
            wmma::store_matrix_sync(scr + nj * 16, acc[mi][nj], 68, wmma::mem_row_major);
        __syncwarp();
        const int irow = i0 + wm * 32 + mi * 16;
        uint32_t* outp = (uint32_t*)(S + ((size_t)b * NPIX + irow) * NPIX + j0 + wc * 64);
        #pragma unroll
        for (int r = 0; r < 16; ++r) {
            float2 v = *(float2*)&scr[r * 68 + lane * 2];
            __half2 h2 = __float22half2_rn(v);
            outp[(size_t)r * (NPIX / 2) + lane] = *(uint32_t*)&h2;
        }
        __syncwarp();
    }
}

// ---------------- kernel 3: softmax row -> q = 0.5*tanh(p/2) bf16 -----------
__global__ void att_kernel(const __half* __restrict__ S,
                           __nv_bfloat16* __restrict__ Aq) {
    const size_t roff = ((size_t)blockIdx.y * NPIX + blockIdx.x) * (size_t)NPIX;
    const __half2* r2 = (const __half2*)(S + roff);
    __nv_bfloat162* o2 = (__nv_bfloat162*)(Aq + roff);
    const int t = threadIdx.x;
    const int lane = t & 31, wid = t >> 5;
    __shared__ float smax[8];
    __shared__ float ssum[8];

    float v[16];
    float mx = -1e30f;
    #pragma unroll
    for (int q = 0; q < 8; ++q) {
        float2 f = __half22float2(r2[t + q * 256]);
        v[2 * q] = f.x; v[2 * q + 1] = f.y;
        mx = fmaxf(mx, fmaxf(f.x, f.y));
    }
    #pragma unroll
    for (int o = 16; o; o >>= 1) mx = fmaxf(mx, __shfl_xor_sync(0xffffffffu, mx, o));
    if (lane == 0) smax[wid] = mx;
    __syncthreads();
    mx = smax[0];
    #pragma unroll
    for (int w = 1; w < 8; ++w) mx = fmaxf(mx, smax[w]);

    float s = 0.f;
    #pragma unroll
    for (int q = 0; q < 16; ++q) { v[q] = __expf(v[q] - mx); s += v[q]; }
    #pragma unroll
    for (int o = 16; o; o >>= 1) s += __shfl_xor_sync(0xffffffffu, s, o);
    if (lane == 0) ssum[wid] = s;
    __syncthreads();
    float Z = 0.f;
    #pragma unroll
    for (int w = 0; w < 8; ++w) Z += ssum[w];
    float inv = 1.0f / Z;

    #pragma unroll
    for (int q = 0; q < 8; ++q) {
        float q0 = 0.5f * tanh_fast(0.5f * (v[2 * q] * inv));
        float q1 = 0.5f * tanh_fast(0.5f * (v[2 * q + 1] * inv));
        o2[t + q * 256] = __floats2bfloat162_rn(q0, q1);
    }
}

// ---------------- kernel 4: out[b,c,m] = x + base[c] - alpha * sum_n q*V ----
#define PV_STAGE_B ((128 * LDT + 256 * LDT) * 2)   // 55296 bytes per stage
#define PV_SMEM    (3 * PV_STAGE_B + 256)          // 166144
#define LDE 260
__global__ __launch_bounds__(256) void pv_wmma_kernel(const __nv_bfloat16* __restrict__ Aq,
                                                      const __nv_bfloat16* __restrict__ VH,
                                                      const float* __restrict__ xres,
                                                      const float* __restrict__ alpha,
                                                      float* __restrict__ out) {
    extern __shared__ char dyn[];
    const int tid = threadIdx.x, w = tid >> 5;
    const int b  = blockIdx.y;
    const int m0 = blockIdx.x * 128;

    uint32_t dynb = smem_u32(dyn);
    uint32_t base = (dynb + 255u) & ~255u;
    char* sb = dyn + (base - dynb);
    const uint32_t sbase = base;

    const __nv_bfloat16* pa = Aq + ((size_t)b * NPIX + m0) * (size_t)NPIX;
    const __nv_bfloat16* pb = VH + (size_t)b * CH * NPIX;

    auto issue_stage = [&](int t) {
        const int s = t % 3;
        const uint32_t dA = sbase + (uint32_t)s * PV_STAGE_B;
        const uint32_t dB = dA + 128 * LDT * 2;
        const int n0 = t << 6;
        #pragma unroll
        for (int p = 0; p < 4; ++p) {           // A: 128 rows x 64 bf16
            int idx = tid + p * 256;
            int row = idx >> 3, c8 = idx & 7;
            cpa16(dA + (uint32_t)(row * LDT + c8 * 8) * 2,
                  pa + (size_t)row * NPIX + n0 + c8 * 8);
        }
        #pragma unroll
        for (int p = 0; p < 8; ++p) {           // B: 256 rows x 64 bf16
            int idx = tid + p * 256;
            int row = idx >> 3, c8 = idx & 7;
            cpa16(dB + (uint32_t)(row * LDT + c8 * 8) * 2,
                  pb + (size_t)row * NPIX + n0 + c8 * 8);
        }
        cpa_commit();
    };

    const int wm = w >> 2;    // 0..1
    const int wc = w & 3;     // 0..3
    wmma::fragment<wmma::accumulator, 16, 16, 16, float> acc[4][4];
    #pragma unroll
    for (int mi = 0; mi < 4; ++mi)
        #pragma unroll
        for (int nj = 0; nj < 4; ++nj) wmma::fill_fragment(acc[mi][nj], 0.0f);

    issue_stage(0);
    issue_stage(1);

    for (int t = 0; t < 64; ++t) {
        if (t < 63) cpa_wait<1>(); else cpa_wait<0>();
        __syncthreads();

        const __nv_bfloat16* cA = (const __nv_bfloat16*)(sb + (size_t)(t % 3) * PV_STAGE_B);
        const __nv_bfloat16* cB = cA + 128 * LDT;
        #pragma unroll
        for (int kk = 0; kk < 64; kk += 16) {
            wmma::fragment<wmma::matrix_a, 16, 16, 16, __nv_bfloat16, wmma::row_major> af[4];
            #pragma unroll
            for (int mi = 0; mi < 4; ++mi)
                wmma::load_matrix_sync(af[mi], cA + (wm * 64 + mi * 16) * LDT + kk, LDT);
            #pragma unroll
            for (int nj = 0; nj < 4; ++nj) {
                wmma::fragment<wmma::matrix_b, 16, 16, 16, __nv_bfloat16, wmma::col_major> bf;
                wmma::load_matrix_sync(bf, cB + (wc * 64 + nj * 16) * LDT + kk, LDT);
                #pragma unroll
                for (int mi = 0; mi < 4; ++mi)
                    wmma::mma_sync(acc[mi][nj], af[mi], bf, acc[mi][nj]);
            }
        }

        if (t + 2 < 64) issue_stage(t + 2);
    }

    // epilogue: stage acc in smem, out = x + base[c] - alpha*acc
    __syncthreads();
    float* Sep = (float*)sb;                     // 128 * LDE * 4 = 133,120 B
    #pragma unroll
    for (int mi = 0; mi < 4; ++mi)
        #pragma unroll
        for (int nj = 0; nj < 4; ++nj)
            wmma::store_matrix_sync(Sep + (wm * 64 + mi * 16) * LDE + wc * 64 + nj * 16,
                                    acc[mi][nj], LDE, wmma::mem_row_major);
    __syncthreads();

    const float al = alpha[0];
    const int ml = tid & 127;
    const int ch = tid >> 7;                     // 0..1
    #pragma unroll 4
    for (int c2 = 0; c2 < 128; ++c2) {
        int c = ch * 128 + c2;
        size_t o = ((size_t)b * CH + c) * NPIX + m0 + ml;
        out[o] = xres[o] + g_base[b * CH + c] - al * Sep[ml * LDE + c];
    }
}

// ---------------- launch ----------------
extern "C" void kernel_launch(void* const* d_in, const int* in_sizes, int n_in,
                              void* d_out, int out_size) {
    const float* x1    = (const float*)d_in[0];
    const float* x2    = (const float*)d_in[1];
    const float* x     = (const float*)d_in[2];
    const float* gamma = (const float*)d_in[3];
    const float* beta  = (const float*)d_in[4];
    const float* mean  = (const float*)d_in[5];
    const float* var   = (const float*)d_in[6];
    const float* Wb    = (const float*)d_in[7];
    const float* bb    = (const float*)d_in[8];
    const float* Wc    = (const float*)d_in[9];
    const float* bc    = (const float*)d_in[10];
    const float* Wd    = (const float*)d_in[11];
    const float* bd    = (const float*)d_in[12];
    const float* alpha = (const float*)d_in[13];
    float* out = (float*)d_out;

    __nv_bfloat16 *Qp, *Kp, *VHp, *Aqp;
    __half* Sp;
    cudaGetSymbolAddress((void**)&Qp,  g_Qb);
    cudaGetSymbolAddress((void**)&Kp,  g_Kb);
    cudaGetSymbolAddress((void**)&VHp, g_VH);
    cudaGetSymbolAddress((void**)&Sp,  g_S);
    cudaGetSymbolAddress((void**)&Aqp, g_Aq);

    cudaFuncSetAttribute(qk_wmma_kernel, cudaFuncAttributeMaxDynamicSharedMemorySize, QK_SMEM);
    cudaFuncSetAttribute(pv_wmma_kernel, cudaFuncAttributeMaxDynamicSharedMemorySize, PV_SMEM);

    // fork side stream: transWd -> projv, colsum -> sumv  (independent of main chain)
    cudaEventRecord(g_evF, 0);
    cudaStreamWaitEvent(g_s2, g_evF, 0);
    transwd_kernel<<<CH, CH, 0, g_s2>>>(Wd);
    colsum_kernel<<<dim3(CH, BATCH), 256, 0, g_s2>>>(x);
    sumv_kernel<<<BATCH, CH, 0, g_s2>>>(Wd, bd, alpha);
    projv_kernel<<<dim3(NPIX / 64, BATCH), 256, 0, g_s2>>>(x, bd, VHp);
    cudaEventRecord(g_evJ, g_s2);

    // main chain
    prep_kernel<<<1, 256>>>(gamma, beta, mean, var);
    foldw_kernel<<<dim3(CKDIM, 2), 256>>>(Wb, bb, Wc, bc);
    projqk_kernel<<<dim3(NPIX / 64, 2, BATCH), 256>>>(x1, x2, Qp, Kp);
    qk_wmma_kernel<<<dim3(NPIX / 128, NPIX / 128, BATCH), 256, QK_SMEM>>>(Qp, Kp, Sp);
    att_kernel<<<dim3(NPIX, BATCH), 256>>>(Sp, Aqp);

    // join, then PV (needs Aq + VH + g_base)
    cudaStreamWaitEvent(0, g_evJ, 0);
    pv_wmma_kernel<<<dim3(NPIX / 128, BATCH), 256, PV_SMEM>>>(Aqp, VHp, x, alpha, out);
}

// round 12
// speedup vs baseline: 2.0336x; 1.0327x over previous
#include <cuda_runtime.h>
#include <cuda_bf16.h>
#include <cuda_fp16.h>
#include <mma.h>
#include <math.h>
#include <stdint.h>

using namespace nvcuda;

#define BATCH 4
#define CH    256
#define CKDIM 64
#define NPIX  4096
#define EPS   1e-5f
#define LDT   72            // bf16 smem tile leading dim

#define DINL __device__ __forceinline__

// ---------------- device scratch (static, allocation-free) ----------------
__device__ __align__(16) float g_scale[CH];
__device__ __align__(16) float g_shift[CH];
__device__ __align__(16) float g_sx  [BATCH * CH];
__device__ __align__(16) float g_base[BATCH * CH];                        // alpha*0.5*SumV
__device__ __align__(16) float g_Wqt [CH * CKDIM];                        // BN-folded, [c][k]
__device__ __align__(16) float g_Wkt [CH * CKDIM];
__device__ __align__(16) float g_bq  [CKDIM];
__device__ __align__(16) float g_bk  [CKDIM];
__device__ __align__(16) float g_Wdt [CH * CH];                           // Wd^T, [c][d]
__device__ __align__(16) __nv_bfloat16 g_Qb[BATCH * NPIX * CKDIM];        // [b][i][64]
__device__ __align__(16) __nv_bfloat16 g_Kb[BATCH * NPIX * CKDIM];        // [b][j][64]
__device__ __align__(16) __nv_bfloat16 g_VH[(size_t)BATCH * CH * NPIX];   // [b][c][n]
__device__ __align__(16) __half        g_S [(size_t)BATCH * NPIX * NPIX]; // fp16 scores
__device__ __align__(16) __nv_bfloat16 g_Aq[(size_t)BATCH * NPIX * NPIX]; // q = sig(p)-0.5

// ---------------- streams/events (static init: no device mem alloc) --------
static cudaStream_t g_s2, g_sB[BATCH];
static cudaEvent_t  g_evRoot, g_evW, g_evJ, g_evB[BATCH];
static struct _StrInit {
    _StrInit() {
        cudaStreamCreateWithFlags(&g_s2, cudaStreamNonBlocking);
        cudaEventCreateWithFlags(&g_evRoot, cudaEventDisableTiming);
        cudaEventCreateWithFlags(&g_evW, cudaEventDisableTiming);
        cudaEventCreateWithFlags(&g_evJ, cudaEventDisableTiming);
        for (int b = 0; b < BATCH; ++b) {
            cudaStreamCreateWithFlags(&g_sB[b], cudaStreamNonBlocking);
            cudaEventCreateWithFlags(&g_evB[b], cudaEventDisableTiming);
        }
    }
} g_strInit;

// ---------------- helpers ----------------
DINL uint32_t smem_u32(const void* p) {
    uint32_t a;
    asm("{ .reg .u64 t; cvta.to.shared.u64 t, %1; cvt.u32.u64 %0, t; }"
        : "=r"(a) : "l"(p));
    return a;
}
DINL void cpa16(uint32_t dst, const void* src) {
    asm volatile("cp.async.cg.shared.global [%0], [%1], 16;"
                 :: "r"(dst), "l"(src) : "memory");
}
DINL void cpa_commit() { asm volatile("cp.async.commit_group;" ::: "memory"); }
template<int N> DINL void cpa_wait() {
    asm volatile("cp.async.wait_group %0;" :: "n"(N) : "memory");
}
DINL float tanh_fast(float x) {
    float y;
    asm("tanh.approx.f32 %0, %1;" : "=f"(y) : "f"(x));
    return y;
}

// ---------------- kernel 0: fold BN ----------------
__global__ void prep_kernel(const float* __restrict__ gamma,
                            const float* __restrict__ beta,
                            const float* __restrict__ mean,
                            const float* __restrict__ var) {
    int c = threadIdx.x;
    if (c < CH) {
        float s = gamma[c] * rsqrtf(var[c] + EPS);
        g_scale[c] = s;
        g_shift[c] = beta[c] - mean[c] * s;
    }
}

// ---------------- kernel 0a: fold BN into Wb/Wc, transpose -> [c][k] --------
__global__ void foldw_kernel(const float* __restrict__ Wb,
                             const float* __restrict__ bb,
                             const float* __restrict__ Wc,
                             const float* __restrict__ bc) {
    const int k = blockIdx.x, which = blockIdx.y;
    const float* W  = which ? Wc : Wb;
    const float* bi = which ? bc : bb;
    float* Wt = which ? g_Wkt : g_Wqt;
    float* bo = which ? g_bk  : g_bq;
    const int c = threadIdx.x;
    float w = W[(size_t)k * CH + c];
    Wt[c * CKDIM + k] = w * g_scale[c];
    float sh = w * g_shift[c];
    #pragma unroll
    for (int o = 16; o; o >>= 1) sh += __shfl_xor_sync(0xffffffffu, sh, o);
    __shared__ float red[8];
    if ((c & 31) == 0) red[c >> 5] = sh;
    __syncthreads();
    if (c == 0) {
        float tot = 0.f;
        #pragma unroll
        for (int w8 = 0; w8 < 8; ++w8) tot += red[w8];
        bo[k] = bi[k] + tot;
    }
}

// ---------------- kernel 0e: transpose Wd -> [c][d] -------------------------
__global__ void transwd_kernel(const float* __restrict__ Wd) {
    const int d = blockIdx.x, c = threadIdx.x;
    g_Wdt[(size_t)c * CH + d] = Wd[(size_t)d * CH + c];
}

// ---------------- kernel 0b: column sums of x -> sx[b][c] -------------------
__global__ void colsum_kernel(const float* __restrict__ x) {
    const int c = blockIdx.x, b = blockIdx.y;
    const float* row = x + ((size_t)b * CH + c) * NPIX;
    const int t = threadIdx.x;
    float s = 0.f;
    #pragma unroll
    for (int q = 0; q < 16; ++q) s += row[t + q * 256];
    #pragma unroll
    for (int o = 16; o; o >>= 1) s += __shfl_xor_sync(0xffffffffu, s, o);
    __shared__ float ws[8];
    if ((t & 31) == 0) ws[t >> 5] = s;
    __syncthreads();
    if (t == 0) {
        float tot = 0.f;
        #pragma unroll
        for (int w = 0; w < 8; ++w) tot += ws[w];
        g_sx[b * CH + c] = tot;
    }
}

// ---------------- kernel 0c: base[b][c] = alpha*0.5*(Wd[c,:]·sx[b,:] + N*bd) -
__global__ void sumv_kernel(const float* __restrict__ Wd,
                            const float* __restrict__ bd,
                            const float* __restrict__ alpha) {
    const int b = blockIdx.x;
    const int c = threadIdx.x;
    __shared__ float sxs[CH];
    sxs[c] = g_sx[b * CH + c];
    __syncthreads();
    float dot = 0.f;
    const float* wr = Wd + (size_t)c * CH;
    #pragma unroll 8
    for (int k = 0; k < CH; ++k) dot += wr[k] * sxs[k];
    g_base[b * CH + c] = alpha[0] * 0.5f * (dot + (float)NPIX * bd[c]);
}

// ---------------- kernel 1a: Q & K projections (per batch) ------------------
// grid (NPIX/64, 2), 256 threads, float4 smem path
__global__ __launch_bounds__(256) void projqk_kernel(const float* __restrict__ x1,
                                                     const float* __restrict__ x2,
                                                     __nv_bfloat16* __restrict__ Qo,
                                                     __nv_bfloat16* __restrict__ Ko,
                                                     int b) {
    __shared__ float As[16][68];   // [c][n]
    __shared__ float Bs[16][68];   // [c][k]
    const int which = blockIdx.y;
    const float* x  = which ? x2 : x1;
    const float* Wt = which ? g_Wkt : g_Wqt;
    const float* bv = which ? g_bk : g_bq;
    __nv_bfloat16* out = which ? Ko : Qo;

    const int n0 = blockIdx.x * 64;
    const float* xb = x + (size_t)b * CH * NPIX;
    const int tid = threadIdx.x;
    const int tk = tid & 15;
    const int tn = tid >> 4;

    float acc[4][4] = {};
    for (int c0 = 0; c0 < CH; c0 += 16) {
        {
            int c16 = tid & 15, cc = tid >> 4;
            *(float4*)&As[cc][c16 * 4] =
                *(const float4*)&xb[(size_t)(c0 + cc) * NPIX + n0 + c16 * 4];
            *(float4*)&Bs[cc][c16 * 4] =
                *(const float4*)&Wt[(size_t)(c0 + cc) * CKDIM + c16 * 4];
        }
        __syncthreads();
        #pragma unroll
        for (int cc = 0; cc < 16; ++cc) {
            float4 a4 = *(float4*)&As[cc][tn * 4];
            float4 w4 = *(float4*)&Bs[cc][tk * 4];
            float av[4] = {a4.x, a4.y, a4.z, a4.w};
            float wv[4] = {w4.x, w4.y, w4.z, w4.w};
            #pragma unroll
            for (int i = 0; i < 4; ++i)
                #pragma unroll
                for (int j = 0; j < 4; ++j) acc[i][j] += av[i] * wv[j];
        }
        __syncthreads();
    }
    const float b0 = bv[tk * 4 + 0], b1 = bv[tk * 4 + 1];
    const float b2 = bv[tk * 4 + 2], b3 = bv[tk * 4 + 3];
    #pragma unroll
    for (int i = 0; i < 4; ++i) {
        int n = n0 + tn * 4 + i;
        __nv_bfloat162 lo = __floats2bfloat162_rn(acc[i][0] + b0, acc[i][1] + b1);
        __nv_bfloat162 hi = __floats2bfloat162_rn(acc[i][2] + b2, acc[i][3] + b3);
        uint2 u;
        u.x = *(uint32_t*)&lo;
        u.y = *(uint32_t*)&hi;
        *(uint2*)&out[((size_t)b * NPIX + n) * CKDIM + tk * 4] = u;
    }
}

// ---------------- kernel 1b: V projection (Wdt pre-transposed) --------------
__global__ __launch_bounds__(256) void projv_kernel(const float* __restrict__ x,
                                                    const float* __restrict__ bd,
                                                    __nv_bfloat16* __restrict__ vh) {
    __shared__ float As[16][68];    // [c][n]
    __shared__ float Bs[16][260];   // [c][d]
    const int b  = blockIdx.y;
    const int n0 = blockIdx.x * 64;
    const float* xb = x + (size_t)b * CH * NPIX;
    const int tid = threadIdx.x;
    const int tn = tid & 15;
    const int td = tid >> 4;

    float acc[16][4] = {};
    for (int c0 = 0; c0 < CH; c0 += 16) {
        {
            int c16 = tid & 15, cc = tid >> 4;
            *(float4*)&As[cc][c16 * 4] =
                *(const float4*)&xb[(size_t)(c0 + cc) * NPIX + n0 + c16 * 4];
        }
        #pragma unroll
        for (int r = 0; r < 4; ++r) {
            int idx = tid + r * 256;
            int cc = idx >> 6, d4 = (idx & 63) * 4;
            *(float4*)&Bs[cc][d4] = *(const float4*)&g_Wdt[(size_t)(c0 + cc) * CH + d4];
        }
        __syncthreads();
        #pragma unroll
        for (int cc = 0; cc < 16; ++cc) {
            float4 a4 = *(float4*)&As[cc][tn * 4];
            float av[4] = {a4.x, a4.y, a4.z, a4.w};
            float wv[16];
            #pragma unroll
            for (int g = 0; g < 4; ++g) {
                float4 w4 = *(float4*)&Bs[cc][td * 16 + g * 4];
                wv[g * 4 + 0] = w4.x; wv[g * 4 + 1] = w4.y;
                wv[g * 4 + 2] = w4.z; wv[g * 4 + 3] = w4.w;
            }
            #pragma unroll
            for (int i = 0; i < 16; ++i)
                #pragma unroll
                for (int j = 0; j < 4; ++j) acc[i][j] += wv[i] * av[j];
        }
        __syncthreads();
    }
    #pragma unroll
    for (int i = 0; i < 16; ++i) {
        int d = td * 16 + i;
        float bdv = bd[d];
        __nv_bfloat162 lo = __floats2bfloat162_rn(acc[i][0] + bdv, acc[i][1] + bdv);
        __nv_bfloat162 hi = __floats2bfloat162_rn(acc[i][2] + bdv, acc[i][3] + bdv);
        uint2 u;
        u.x = *(uint32_t*)&lo;
        u.y = *(uint32_t*)&hi;
        *(uint2*)&vh[((size_t)b * CH + d) * NPIX + n0 + tn * 4] = u;
    }
}

// ---------------- kernel 2: scores = Q @ K^T via wmma bf16 -> fp16 S --------
#define QK_OFF_K   18432
#define QK_OFF_SCR 36864
#define QK_SMEM    (36864 + 8 * 16 * 68 * 4)   // 71680
__global__ __launch_bounds__(256) void qk_wmma_kernel(const __nv_bfloat16* __restrict__ Qb,
                                                      const __nv_bfloat16* __restrict__ Kb,
                                                      __half* __restrict__ S, int b) {
    extern __shared__ char dyn[];
    __nv_bfloat16* Qs = (__nv_bfloat16*)(dyn);
    __nv_bfloat16* Ks = (__nv_bfloat16*)(dyn + QK_OFF_K);
    const int tid = threadIdx.x, w = tid >> 5, lane = tid & 31;
    float* scr = (float*)(dyn + QK_OFF_SCR) + w * (16 * 68);

    const int i0 = blockIdx.y * 128;
    const int j0 = blockIdx.x * 128;

    const uint4* gQ = (const uint4*)(Qb + ((size_t)b * NPIX + i0) * CKDIM);
    const uint4* gK = (const uint4*)(Kb + ((size_t)b * NPIX + j0) * CKDIM);
    #pragma unroll
    for (int p = 0; p < 4; ++p) {
        int idx = tid + p * 256;
        int row = idx >> 3, c8 = idx & 7;
        *(uint4*)&Qs[row * LDT + c8 * 8] = gQ[idx];
        *(uint4*)&Ks[row * LDT + c8 * 8] = gK[idx];
    }
    __syncthreads();

    const int wm = w >> 1, wc = w & 1;
    wmma::fragment<wmma::accumulator, 16, 16, 16, float> acc[2][4];
    #pragma unroll
    for (int mi = 0; mi < 2; ++mi)
        #pragma unroll
        for (int nj = 0; nj < 4; ++nj) wmma::fill_fragment(acc[mi][nj], 0.0f);

    #pragma unroll
    for (int kk = 0; kk < 64; kk += 16) {
        wmma::fragment<wmma::matrix_a, 16, 16, 16, __nv_bfloat16, wmma::row_major> af[2];
        wmma::load_matrix_sync(af[0], Qs + (wm * 32 +  0) * LDT + kk, LDT);
        wmma::load_matrix_sync(af[1], Qs + (wm * 32 + 16) * LDT + kk, LDT);
        #pragma unroll
        for (int nj = 0; nj < 4; ++nj) {
            wmma::fragment<wmma::matrix_b, 16, 16, 16, __nv_bfloat16, wmma::col_major> bf;
            wmma::load_matrix_sync(bf, Ks + (wc * 64 + nj * 16) * LDT + kk, LDT);
            wmma::mma_sync(acc[0][nj], af[0], bf, acc[0][nj]);
            wmma::mma_sync(acc[1][nj], af[1], bf, acc[1][nj]);
        }
    }

    #pragma unroll
    for (int mi = 0; mi < 2; ++mi) {
        #pragma unroll
        for (int nj = 0; nj < 4; ++nj)
            wmma::store_matrix_sync(scr + nj * 16, acc[mi][nj], 68, wmma::mem_row_major);
        __syncwarp();
        const int irow = i0 + wm * 32 + mi * 16;
        uint32_t* outp = (uint32_t*)(S + ((size_t)b * NPIX + irow) * NPIX + j0 + wc * 64);
        #pragma unroll
        for (int r = 0; r < 16; ++r) {
            float2 v = *(float2*)&scr[r * 68 + lane * 2];
            __half2 h2 = __float22half2_rn(v);
            outp[(size_t)r * (NPIX / 2) + lane] = *(uint32_t*)&h2;
        }
        __syncwarp();
    }
}

// ---------------- kernel 3: softmax row -> q = 0.5*tanh(p/2) bf16 -----------
__global__ void att_kernel(const __half* __restrict__ S,
                           __nv_bfloat16* __restrict__ Aq, int b) {
    const size_t roff = ((size_t)b * NPIX + blockIdx.x) * (size_t)NPIX;
    const __half2* r2 = (const __half2*)(S + roff);
    __nv_bfloat162* o2 = (__nv_bfloat162*)(Aq + roff);
    const int t = threadIdx.x;
    const int lane = t & 31, wid = t >> 5;
    __shared__ float smax[8];
    __shared__ float ssum[8];

    float v[16];
    float mx = -1e30f;
    #pragma unroll
    for (int q = 0; q < 8; ++q) {
        float2 f = __half22float2(r2[t + q * 256]);
        v[2 * q] = f.x; v[2 * q + 1] = f.y;
        mx = fmaxf(mx, fmaxf(f.x, f.y));
    }
    #pragma unroll
    for (int o = 16; o; o >>= 1) mx = fmaxf(mx, __shfl_xor_sync(0xffffffffu, mx, o));
    if (lane == 0) smax[wid] = mx;
    __syncthreads();
    mx = smax[0];
    #pragma unroll
    for (int w = 1; w < 8; ++w) mx = fmaxf(mx, smax[w]);

    float s = 0.f;
    #pragma unroll
    for (int q = 0; q < 16; ++q) { v[q] = __expf(v[q] - mx); s += v[q]; }
    #pragma unroll
    for (int o = 16; o; o >>= 1) s += __shfl_xor_sync(0xffffffffu, s, o);
    if (lane == 0) ssum[wid] = s;
    __syncthreads();
    float Z = 0.f;
    #pragma unroll
    for (int w = 0; w < 8; ++w) Z += ssum[w];
    float inv = 1.0f / Z;

    #pragma unroll
    for (int q = 0; q < 8; ++q) {
        float q0 = 0.5f * tanh_fast(0.5f * (v[2 * q] * inv));
        float q1 = 0.5f * tanh_fast(0.5f * (v[2 * q + 1] * inv));
        o2[t + q * 256] = __floats2bfloat162_rn(q0, q1);
    }
}

// ---------------- kernel 4: out[b,c,m] = x + base[c] - alpha * sum_n q*V ----
#define PV_STAGE_B ((128 * LDT + 256 * LDT) * 2)   // 55296 bytes per stage
#define PV_SMEM    (3 * PV_STAGE_B + 256)          // 166144
#define LDE 260
__global__ __launch_bounds__(256) void pv_wmma_kernel(const __nv_bfloat16* __restrict__ Aq,
                                                      const __nv_bfloat16* __restrict__ VH,
                                                      const float* __restrict__ xres,
                                                      const float* __restrict__ alpha,
                                                      float* __restrict__ out, int b) {
    extern __shared__ char dyn[];
    const int tid = threadIdx.x, w = tid >> 5;
    const int m0 = blockIdx.x * 128;

    uint32_t dynb = smem_u32(dyn);
    uint32_t base = (dynb + 255u) & ~255u;
    char* sb = dyn + (base - dynb);
    const uint32_t sbase = base;

    const __nv_bfloat16* pa = Aq + ((size_t)b * NPIX + m0) * (size_t)NPIX;
    const __nv_bfloat16* pb = VH + (size_t)b * CH * NPIX;

    auto issue_stage = [&](int t) {
        const int s = t % 3;
        const uint32_t dA = sbase + (uint32_t)s * PV_STAGE_B;
        const uint32_t dB = dA + 128 * LDT * 2;
        const int n0 = t << 6;
        #pragma unroll
        for (int p = 0; p < 4; ++p) {           // A: 128 rows x 64 bf16
            int idx = tid + p * 256;
            int row = idx >> 3, c8 = idx & 7;
            cpa16(dA + (uint32_t)(row * LDT + c8 * 8) * 2,
                  pa + (size_t)row * NPIX + n0 + c8 * 8);
        }
        #pragma unroll
        for (int p = 0; p < 8; ++p) {           // B: 256 rows x 64 bf16
            int idx = tid + p * 256;
            int row = idx >> 3, c8 = idx & 7;
            cpa16(dB + (uint32_t)(row * LDT + c8 * 8) * 2,
                  pb + (size_t)row * NPIX + n0 + c8 * 8);
        }
        cpa_commit();
    };

    const int wm = w >> 2;    // 0..1
    const int wc = w & 3;     // 0..3
    wmma::fragment<wmma::accumulator, 16, 16, 16, float> acc[4][4];
    #pragma unroll
    for (int mi = 0; mi < 4; ++mi)
        #pragma unroll
        for (int nj = 0; nj < 4; ++nj) wmma::fill_fragment(acc[mi][nj], 0.0f);

    issue_stage(0);
    issue_stage(1);

    for (int t = 0; t < 64; ++t) {
        if (t < 63) cpa_wait<1>(); else cpa_wait<0>();
        __syncthreads();

        const __nv_bfloat16* cA = (const __nv_bfloat16*)(sb + (size_t)(t % 3) * PV_STAGE_B);
        const __nv_bfloat16* cB = cA + 128 * LDT;
        #pragma unroll
        for (int kk = 0; kk < 64; kk += 16) {
            wmma::fragment<wmma::matrix_a, 16, 16, 16, __nv_bfloat16, wmma::row_major> af[4];
            #pragma unroll
            for (int mi = 0; mi < 4; ++mi)
                wmma::load_matrix_sync(af[mi], cA + (wm * 64 + mi * 16) * LDT + kk, LDT);
            #pragma unroll
            for (int nj = 0; nj < 4; ++nj) {
                wmma::fragment<wmma::matrix_b, 16, 16, 16, __nv_bfloat16, wmma::col_major> bf;
                wmma::load_matrix_sync(bf, cB + (wc * 64 + nj * 16) * LDT + kk, LDT);
                #pragma unroll
                for (int mi = 0; mi < 4; ++mi)
                    wmma::mma_sync(acc[mi][nj], af[mi], bf, acc[mi][nj]);
            }
        }

        if (t + 2 < 64) issue_stage(t + 2);
    }

    // epilogue: stage acc in smem, out = x + base[c] - alpha*acc
    __syncthreads();
    float* Sep = (float*)sb;                     // 128 * LDE * 4 = 133,120 B
    #pragma unroll
    for (int mi = 0; mi < 4; ++mi)
        #pragma unroll
        for (int nj = 0; nj < 4; ++nj)
            wmma::store_matrix_sync(Sep + (wm * 64 + mi * 16) * LDE + wc * 64 + nj * 16,
                                    acc[mi][nj], LDE, wmma::mem_row_major);
    __syncthreads();

    const float al = alpha[0];
    const int ml = tid & 127;
    const int ch = tid >> 7;                     // 0..1
    #pragma unroll 4
    for (int c2 = 0; c2 < 128; ++c2) {
        int c = ch * 128 + c2;
        size_t o = ((size_t)b * CH + c) * NPIX + m0 + ml;
        out[o] = xres[o] + g_base[b * CH + c] - al * Sep[ml * LDE + c];
    }
}

// ---------------- launch ----------------
extern "C" void kernel_launch(void* const* d_in, const int* in_sizes, int n_in,
                              void* d_out, int out_size) {
    const float* x1    = (const float*)d_in[0];
    const float* x2    = (const float*)d_in[1];
    const float* x     = (const float*)d_in[2];
    const float* gamma = (const float*)d_in[3];
    const float* beta  = (const float*)d_in[4];
    const float* mean  = (const float*)d_in[5];
    const float* var   = (const float*)d_in[6];
    const float* Wb    = (const float*)d_in[7];
    const float* bb    = (const float*)d_in[8];
    const float* Wc    = (const float*)d_in[9];
    const float* bc    = (const float*)d_in[10];
    const float* Wd    = (const float*)d_in[11];
    const float* bd    = (const float*)d_in[12];
    const float* alpha = (const float*)d_in[13];
    float* out = (float*)d_out;

    __nv_bfloat16 *Qp, *Kp, *VHp, *Aqp;
    __half* Sp;
    cudaGetSymbolAddress((void**)&Qp,  g_Qb);
    cudaGetSymbolAddress((void**)&Kp,  g_Kb);
    cudaGetSymbolAddress((void**)&VHp, g_VH);
    cudaGetSymbolAddress((void**)&Sp,  g_S);
    cudaGetSymbolAddress((void**)&Aqp, g_Aq);

    cudaFuncSetAttribute(qk_wmma_kernel, cudaFuncAttributeMaxDynamicSharedMemorySize, QK_SMEM);
    cudaFuncSetAttribute(pv_wmma_kernel, cudaFuncAttributeMaxDynamicSharedMemorySize, PV_SMEM);

    // fork all side/batch streams from capture root
    cudaEventRecord(g_evRoot, 0);
    cudaStreamWaitEvent(g_s2, g_evRoot, 0);
    for (int b = 0; b < BATCH; ++b) cudaStreamWaitEvent(g_sB[b], g_evRoot, 0);

    // side stream: Wd transpose -> V projection; colsum -> base
    transwd_kernel<<<CH, CH, 0, g_s2>>>(Wd);
    colsum_kernel<<<dim3(CH, BATCH), 256, 0, g_s2>>>(x);
    sumv_kernel<<<BATCH, CH, 0, g_s2>>>(Wd, bd, alpha);
    projv_kernel<<<dim3(NPIX / 64, BATCH), 256, 0, g_s2>>>(x, bd, VHp);
    cudaEventRecord(g_evJ, g_s2);

    // weight prep on default stream
    prep_kernel<<<1, 256>>>(gamma, beta, mean, var);
    foldw_kernel<<<dim3(CKDIM, 2), 256>>>(Wb, bb, Wc, bc);
    cudaEventRecord(g_evW, 0);

    // per-batch pipelines
    for (int b = 0; b < BATCH; ++b) {
        cudaStream_t s = g_sB[b];
        cudaStreamWaitEvent(s, g_evW, 0);
        projqk_kernel<<<dim3(NPIX / 64, 2), 256, 0, s>>>(x1, x2, Qp, Kp, b);
        qk_wmma_kernel<<<dim3(NPIX / 128, NPIX / 128), 256, QK_SMEM, s>>>(Qp, Kp, Sp, b);
        att_kernel<<<NPIX, 256, 0, s>>>(Sp, Aqp, b);
        cudaStreamWaitEvent(s, g_evJ, 0);
        pv_wmma_kernel<<<dim3(NPIX / 128), 256, PV_SMEM, s>>>(Aqp, VHp, x, alpha, out, b);
        cudaEventRecord(g_evB[b], s);
    }

    // join all batch streams into the capture stream
    for (int b = 0; b < BATCH; ++b) cudaStreamWaitEvent(0, g_evB[b], 0);
}

// round 13
// speedup vs baseline: 2.1284x; 1.0466x over previous
#include <cuda_runtime.h>
#include <cuda_bf16.h>
#include <cuda_fp16.h>
#include <mma.h>
#include <math.h>
#include <stdint.h>

using namespace nvcuda;

#define BATCH 4
#define CH    256
#define CKDIM 64
#define NPIX  4096
#define EPS   1e-5f
#define LDT   72            // bf16 smem tile leading dim (qk/pv)
#define PJ_LDA 136          // projections: col-major A ld (bf16)

#define DINL __device__ __forceinline__

// ---------------- device scratch (static, allocation-free) ----------------
__device__ __align__(16) float g_scale[CH];
__device__ __align__(16) float g_shift[CH];
__device__ __align__(16) float g_sx  [BATCH * CH];
__device__ __align__(16) float g_base[BATCH * CH];                        // alpha*0.5*SumV
__device__ __align__(16) float g_Wqt [CH * CKDIM];                        // BN-folded, [c][k]
__device__ __align__(16) float g_Wkt [CH * CKDIM];
__device__ __align__(16) float g_bq  [CKDIM];
__device__ __align__(16) float g_bk  [CKDIM];
__device__ __align__(16) float g_Wdt [CH * CH];                           // Wd^T, [c][d]
__device__ __align__(16) __nv_bfloat16 g_Qb[BATCH * NPIX * CKDIM];        // [b][i][64]
__device__ __align__(16) __nv_bfloat16 g_Kb[BATCH * NPIX * CKDIM];        // [b][j][64]
__device__ __align__(16) __nv_bfloat16 g_VH[(size_t)BATCH * CH * NPIX];   // [b][c][n]
__device__ __align__(16) __half        g_S [(size_t)BATCH * NPIX * NPIX]; // fp16 scores
__device__ __align__(16) __nv_bfloat16 g_Aq[(size_t)BATCH * NPIX * NPIX]; // q = sig(p)-0.5

// ---------------- streams/events (static init: no device mem alloc) --------
static cudaStream_t g_s2, g_sB[BATCH];
static cudaEvent_t  g_evRoot, g_evW, g_evJ, g_evB[BATCH];
static struct _StrInit {
    _StrInit() {
        cudaStreamCreateWithFlags(&g_s2, cudaStreamNonBlocking);
        cudaEventCreateWithFlags(&g_evRoot, cudaEventDisableTiming);
        cudaEventCreateWithFlags(&g_evW, cudaEventDisableTiming);
        cudaEventCreateWithFlags(&g_evJ, cudaEventDisableTiming);
        for (int b = 0; b < BATCH; ++b) {
            cudaStreamCreateWithFlags(&g_sB[b], cudaStreamNonBlocking);
            cudaEventCreateWithFlags(&g_evB[b], cudaEventDisableTiming);
        }
    }
} g_strInit;

// ---------------- helpers ----------------
DINL uint32_t smem_u32(const void* p) {
    uint32_t a;
    asm("{ .reg .u64 t; cvta.to.shared.u64 t, %1; cvt.u32.u64 %0, t; }"
        : "=r"(a) : "l"(p));
    return a;
}
DINL void cpa16(uint32_t dst, const void* src) {
    asm volatile("cp.async.cg.shared.global [%0], [%1], 16;"
                 :: "r"(dst), "l"(src) : "memory");
}
DINL void cpa_commit() { asm volatile("cp.async.commit_group;" ::: "memory"); }
template<int N> DINL void cpa_wait() {
    asm volatile("cp.async.wait_group %0;" :: "n"(N) : "memory");
}
DINL float tanh_fast(float x) {
    float y;
    asm("tanh.approx.f32 %0, %1;" : "=f"(y) : "f"(x));
    return y;
}

// ---------------- kernel 0: fold BN ----------------
__global__ void prep_kernel(const float* __restrict__ gamma,
                            const float* __restrict__ beta,
                            const float* __restrict__ mean,
                            const float* __restrict__ var) {
    int c = threadIdx.x;
    if (c < CH) {
        float s = gamma[c] * rsqrtf(var[c] + EPS);
        g_scale[c] = s;
        g_shift[c] = beta[c] - mean[c] * s;
    }
}

// ---------------- kernel 0a: fold BN into Wb/Wc, transpose -> [c][k] --------
__global__ void foldw_kernel(const float* __restrict__ Wb,
                             const float* __restrict__ bb,
                             const float* __restrict__ Wc,
                             const float* __restrict__ bc) {
    const int k = blockIdx.x, which = blockIdx.y;
    const float* W  = which ? Wc : Wb;
    const float* bi = which ? bc : bb;
    float* Wt = which ? g_Wkt : g_Wqt;
    float* bo = which ? g_bk  : g_bq;
    const int c = threadIdx.x;
    float w = W[(size_t)k * CH + c];
    Wt[c * CKDIM + k] = w * g_scale[c];
    float sh = w * g_shift[c];
    #pragma unroll
    for (int o = 16; o; o >>= 1) sh += __shfl_xor_sync(0xffffffffu, sh, o);
    __shared__ float red[8];
    if ((c & 31) == 0) red[c >> 5] = sh;
    __syncthreads();
    if (c == 0) {
        float tot = 0.f;
        #pragma unroll
        for (int w8 = 0; w8 < 8; ++w8) tot += red[w8];
        bo[k] = bi[k] + tot;
    }
}

// ---------------- kernel 0e: transpose Wd -> [c][d] -------------------------
__global__ void transwd_kernel(const float* __restrict__ Wd) {
    const int d = blockIdx.x, c = threadIdx.x;
    g_Wdt[(size_t)c * CH + d] = Wd[(size_t)d * CH + c];
}

// ---------------- kernel 0b: column sums of x -> sx[b][c] -------------------
__global__ void colsum_kernel(const float* __restrict__ x) {
    const int c = blockIdx.x, b = blockIdx.y;
    const float* row = x + ((size_t)b * CH + c) * NPIX;
    const int t = threadIdx.x;
    float s = 0.f;
    #pragma unroll
    for (int q = 0; q < 16; ++q) s += row[t + q * 256];
    #pragma unroll
    for (int o = 16; o; o >>= 1) s += __shfl_xor_sync(0xffffffffu, s, o);
    __shared__ float ws[8];
    if ((t & 31) == 0) ws[t >> 5] = s;
    __syncthreads();
    if (t == 0) {
        float tot = 0.f;
        #pragma unroll
        for (int w = 0; w < 8; ++w) tot += ws[w];
        g_sx[b * CH + c] = tot;
    }
}

// ---------------- kernel 0c: base[b][c] = alpha*0.5*(Wd[c,:]·sx[b,:] + N*bd) -
__global__ void sumv_kernel(const float* __restrict__ Wd,
                            const float* __restrict__ bd,
                            const float* __restrict__ alpha) {
    const int b = blockIdx.x;
    const int c = threadIdx.x;
    __shared__ float sxs[CH];
    sxs[c] = g_sx[b * CH + c];
    __syncthreads();
    float dot = 0.f;
    const float* wr = Wd + (size_t)c * CH;
    #pragma unroll 8
    for (int k = 0; k < CH; ++k) dot += wr[k] * sxs[k];
    g_base[b * CH + c] = alpha[0] * 0.5f * (dot + (float)NPIX * bd[c]);
}

// ---------------- kernel 1a: Q & K projections via wmma (per batch) ---------
// grid (NPIX/128, 2); CTA: 128 n x 64 k; 8 warps = 4(n) x 2(k)
__global__ __launch_bounds__(256) void projqk_kernel(const float* __restrict__ x1,
                                                     const float* __restrict__ x2,
                                                     __nv_bfloat16* __restrict__ Qo,
                                                     __nv_bfloat16* __restrict__ Ko,
                                                     int b) {
    __shared__ __align__(16) char sm[35840];
    __nv_bfloat16* As = (__nv_bfloat16*)sm;             // col-major (n x c): [cc][nn], ld=PJ_LDA
    __nv_bfloat16* Bs = (__nv_bfloat16*)(sm + 4608);    // row-major (c x k): [cc][k], ld=64
    float* scr = (float*)sm;                            // epilogue: [128][68] fp32

    const int which = blockIdx.y;
    const float* x  = which ? x2 : x1;
    const float* Wt = which ? g_Wkt : g_Wqt;
    const float* bv = which ? g_bk : g_bq;
    __nv_bfloat16* out = which ? Ko : Qo;

    const int n0 = blockIdx.x * 128;
    const float* xb = x + (size_t)b * CH * NPIX;
    const int tid = threadIdx.x, w = tid >> 5;
    const int wm = w >> 1, wk = w & 1;

    wmma::fragment<wmma::accumulator, 16, 16, 16, float> acc[2][2];
    #pragma unroll
    for (int mi = 0; mi < 2; ++mi)
        #pragma unroll
        for (int nj = 0; nj < 2; ++nj) wmma::fill_fragment(acc[mi][nj], 0.0f);

    for (int c0 = 0; c0 < CH; c0 += 16) {
        #pragma unroll
        for (int p = 0; p < 8; ++p) {               // A tile: 16c x 128n
            int idx = tid + p * 256;
            int cc = idx >> 7, nn = idx & 127;
            As[cc * PJ_LDA + nn] =
                __float2bfloat16(xb[(size_t)(c0 + cc) * NPIX + n0 + nn]);
        }
        #pragma unroll
        for (int p = 0; p < 4; ++p) {               // B tile: 16c x 64k
            int idx = tid + p * 256;
            int cc = idx >> 6, k = idx & 63;
            Bs[cc * 64 + k] = __float2bfloat16(Wt[(size_t)(c0 + cc) * CKDIM + k]);
        }
        __syncthreads();
        wmma::fragment<wmma::matrix_a, 16, 16, 16, __nv_bfloat16, wmma::col_major> af[2];
        wmma::fragment<wmma::matrix_b, 16, 16, 16, __nv_bfloat16, wmma::row_major> bf[2];
        #pragma unroll
        for (int mi = 0; mi < 2; ++mi)
            wmma::load_matrix_sync(af[mi], As + wm * 32 + mi * 16, PJ_LDA);
        #pragma unroll
        for (int nj = 0; nj < 2; ++nj)
            wmma::load_matrix_sync(bf[nj], Bs + wk * 32 + nj * 16, 64);
        #pragma unroll
        for (int mi = 0; mi < 2; ++mi)
            #pragma unroll
            for (int nj = 0; nj < 2; ++nj)
                wmma::mma_sync(acc[mi][nj], af[mi], bf[nj], acc[mi][nj]);
        __syncthreads();
    }

    // epilogue: stage fp32, add bias, bf16, coalesced write to [n][64]
    #pragma unroll
    for (int mi = 0; mi < 2; ++mi)
        #pragma unroll
        for (int nj = 0; nj < 2; ++nj)
            wmma::store_matrix_sync(scr + (wm * 32 + mi * 16) * 68 + wk * 32 + nj * 16,
                                    acc[mi][nj], 68, wmma::mem_row_major);
    __syncthreads();
    const int n = tid >> 1;
    const int ks = (tid & 1) * 32;
    __nv_bfloat16* orow = out + ((size_t)b * NPIX + n0 + n) * CKDIM + ks;
    #pragma unroll
    for (int j = 0; j < 8; ++j) {
        float4 v = *(float4*)&scr[n * 68 + ks + j * 4];
        const float* bp = bv + ks + j * 4;
        __nv_bfloat162 lo = __floats2bfloat162_rn(v.x + bp[0], v.y + bp[1]);
        __nv_bfloat162 hi = __floats2bfloat162_rn(v.z + bp[2], v.w + bp[3]);
        uint2 u;
        u.x = *(uint32_t*)&lo;
        u.y = *(uint32_t*)&hi;
        *(uint2*)&orow[j * 4] = u;
    }
}

// ---------------- kernel 1b: V projection via wmma --------------------------
// grid (NPIX/128, CH/128, BATCH); CTA: 128 n x 128 d; 8 warps = 4(n) x 2(d)
#define PJV_SMEM (128 * 132 * 4 + 128)   // 67712
__global__ __launch_bounds__(256) void projv_kernel(const float* __restrict__ x,
                                                    const float* __restrict__ bd,
                                                    __nv_bfloat16* __restrict__ vh) {
    extern __shared__ char dyn[];
    __nv_bfloat16* As = (__nv_bfloat16*)dyn;            // col-major (n x c), ld=PJ_LDA
    __nv_bfloat16* Bs = (__nv_bfloat16*)(dyn + 4608);   // row-major (c x d), ld=128
    float* scr = (float*)dyn;                           // epilogue: col-major [d][132n]

    const int b  = blockIdx.z;
    const int n0 = blockIdx.x * 128;
    const int d0 = blockIdx.y * 128;
    const float* xb = x + (size_t)b * CH * NPIX;
    const int tid = threadIdx.x, w = tid >> 5;
    const int wm = w >> 1, wd = w & 1;

    wmma::fragment<wmma::accumulator, 16, 16, 16, float> acc[2][4];
    #pragma unroll
    for (int mi = 0; mi < 2; ++mi)
        #pragma unroll
        for (int nj = 0; nj < 4; ++nj) wmma::fill_fragment(acc[mi][nj], 0.0f);

    for (int c0 = 0; c0 < CH; c0 += 16) {
        #pragma unroll
        for (int p = 0; p < 8; ++p) {               // A tile: 16c x 128n
            int idx = tid + p * 256;
            int cc = idx >> 7, nn = idx & 127;
            As[cc * PJ_LDA + nn] =
                __float2bfloat16(xb[(size_t)(c0 + cc) * NPIX + n0 + nn]);
        }
        #pragma unroll
        for (int p = 0; p < 8; ++p) {               // B tile: 16c x 128d
            int idx = tid + p * 256;
            int cc = idx >> 7, dd = idx & 127;
            Bs[cc * 128 + dd] = __float2bfloat16(g_Wdt[(size_t)(c0 + cc) * CH + d0 + dd]);
        }
        __syncthreads();
        wmma::fragment<wmma::matrix_a, 16, 16, 16, __nv_bfloat16, wmma::col_major> af[2];
        #pragma unroll
        for (int mi = 0; mi < 2; ++mi)
            wmma::load_matrix_sync(af[mi], As + wm * 32 + mi * 16, PJ_LDA);
        #pragma unroll
        for (int nj = 0; nj < 4; ++nj) {
            wmma::fragment<wmma::matrix_b, 16, 16, 16, __nv_bfloat16, wmma::row_major> bf;
            wmma::load_matrix_sync(bf, Bs + wd * 64 + nj * 16, 128);
            #pragma unroll
            for (int mi = 0; mi < 2; ++mi)
                wmma::mma_sync(acc[mi][nj], af[mi], bf, acc[mi][nj]);
        }
        __syncthreads();
    }

    // epilogue: col-major stage (n fast), add bias, bf16, coalesced write [d][n]
    #pragma unroll
    for (int mi = 0; mi < 2; ++mi)
        #pragma unroll
        for (int nj = 0; nj < 4; ++nj)
            wmma::store_matrix_sync(scr + (wd * 64 + nj * 16) * 132 + wm * 32 + mi * 16,
                                    acc[mi][nj], 132, wmma::mem_col_major);
    __syncthreads();
    #pragma unroll
    for (int ds = 0; ds < 16; ++ds) {
        int dcol = (tid >> 5) + ds * 8;
        int n4   = (tid & 31) * 4;
        float bdv = bd[d0 + dcol];
        float4 v = *(float4*)&scr[dcol * 132 + n4];
        __nv_bfloat162 lo = __floats2bfloat162_rn(v.x + bdv, v.y + bdv);
        __nv_bfloat162 hi = __floats2bfloat162_rn(v.z + bdv, v.w + bdv);
        uint2 u;
        u.x = *(uint32_t*)&lo;
        u.y = *(uint32_t*)&hi;
        *(uint2*)&vh[((size_t)b * CH + d0 + dcol) * NPIX + n0 + n4] = u;
    }
}

// ---------------- kernel 2: scores = Q @ K^T via wmma bf16 -> fp16 S --------
#define QK_OFF_K   18432
#define QK_OFF_SCR 36864
#define QK_SMEM    (36864 + 8 * 16 * 68 * 4)   // 71680
__global__ __launch_bounds__(256) void qk_wmma_kernel(const __nv_bfloat16* __restrict__ Qb,
                                                      const __nv_bfloat16* __restrict__ Kb,
                                                      __half* __restrict__ S, int b) {
    extern __shared__ char dyn[];
    __nv_bfloat16* Qs = (__nv_bfloat16*)(dyn);
    __nv_bfloat16* Ks = (__nv_bfloat16*)(dyn + QK_OFF_K);
    const int tid = threadIdx.x, w = tid >> 5, lane = tid & 31;
    float* scr = (float*)(dyn + QK_OFF_SCR) + w * (16 * 68);

    const int i0 = blockIdx.y * 128;
    const int j0 = blockIdx.x * 128;

    const uint4* gQ = (const uint4*)(Qb + ((size_t)b * NPIX + i0) * CKDIM);
    const uint4* gK = (const uint4*)(Kb + ((size_t)b * NPIX + j0) * CKDIM);
    #pragma unroll
    for (int p = 0; p < 4; ++p) {
        int idx = tid + p * 256;
        int row = idx >> 3, c8 = idx & 7;
        *(uint4*)&Qs[row * LDT + c8 * 8] = gQ[idx];
        *(uint4*)&Ks[row * LDT + c8 * 8] = gK[idx];
    }
    __syncthreads();

    const int wm = w >> 1, wc = w & 1;
    wmma::fragment<wmma::accumulator, 16, 16, 16, float> acc[2][4];
    #pragma unroll
    for (int mi = 0; mi < 2; ++mi)
        #pragma unroll
        for (int nj = 0; nj < 4; ++nj) wmma::fill_fragment(acc[mi][nj], 0.0f);

    #pragma unroll
    for (int kk = 0; kk < 64; kk += 16) {
        wmma::fragment<wmma::matrix_a, 16, 16, 16, __nv_bfloat16, wmma::row_major> af[2];
        wmma::load_matrix_sync(af[0], Qs + (wm * 32 +  0) * LDT + kk, LDT);
        wmma::load_matrix_sync(af[1], Qs + (wm * 32 + 16) * LDT + kk, LDT);
        #pragma unroll
        for (int nj = 0; nj < 4; ++nj) {
            wmma::fragment<wmma::matrix_b, 16, 16, 16, __nv_bfloat16, wmma::col_major> bf;
            wmma::load_matrix_sync(bf, Ks + (wc * 64 + nj * 16) * LDT + kk, LDT);
            wmma::mma_sync(acc[0][nj], af[0], bf, acc[0][nj]);
            wmma::mma_sync(acc[1][nj], af[1], bf, acc[1][nj]);
        }
    }

    #pragma unroll
    for (int mi = 0; mi < 2; ++mi) {
        #pragma unroll
        for (int nj = 0; nj < 4; ++nj)
            wmma::store_matrix_sync(scr + nj * 16, acc[mi][nj], 68, wmma::mem_row_major);
        __syncwarp();
        const int irow = i0 + wm * 32 + mi * 16;
        uint32_t* outp = (uint32_t*)(S + ((size_t)b * NPIX + irow) * NPIX + j0 + wc * 64);
        #pragma unroll
        for (int r = 0; r < 16; ++r) {
            float2 v = *(float2*)&scr[r * 68 + lane * 2];
            __half2 h2 = __float22half2_rn(v);
            outp[(size_t)r * (NPIX / 2) + lane] = *(uint32_t*)&h2;
        }
        __syncwarp();
    }
}

// ---------------- kernel 3: softmax row -> q = 0.5*tanh(p/2) bf16 -----------
__global__ void att_kernel(const __half* __restrict__ S,
                           __nv_bfloat16* __restrict__ Aq, int b) {
    const size_t roff = ((size_t)b * NPIX + blockIdx.x) * (size_t)NPIX;
    const __half2* r2 = (const __half2*)(S + roff);
    __nv_bfloat162* o2 = (__nv_bfloat162*)(Aq + roff);
    const int t = threadIdx.x;
    const int lane = t & 31, wid = t >> 5;
    __shared__ float smax[8];
    __shared__ float ssum[8];

    float v[16];
    float mx = -1e30f;
    #pragma unroll
    for (int q = 0; q < 8; ++q) {
        float2 f = __half22float2(r2[t + q * 256]);
        v[2 * q] = f.x; v[2 * q + 1] = f.y;
        mx = fmaxf(mx, fmaxf(f.x, f.y));
    }
    #pragma unroll
    for (int o = 16; o; o >>= 1) mx = fmaxf(mx, __shfl_xor_sync(0xffffffffu, mx, o));
    if (lane == 0) smax[wid] = mx;
    __syncthreads();
    mx = smax[0];
    #pragma unroll
    for (int w = 1; w < 8; ++w) mx = fmaxf(mx, smax[w]);

    float s = 0.f;
    #pragma unroll
    for (int q = 0; q < 16; ++q) { v[q] = __expf(v[q] - mx); s += v[q]; }
    #pragma unroll
    for (int o = 16; o; o >>= 1) s += __shfl_xor_sync(0xffffffffu, s, o);
    if (lane == 0) ssum[wid] = s;
    __syncthreads();
    float Z = 0.f;
    #pragma unroll
    for (int w = 0; w < 8; ++w) Z += ssum[w];
    float inv = 1.0f / Z;

    #pragma unroll
    for (int q = 0; q < 8; ++q) {
        float q0 = 0.5f * tanh_fast(0.5f * (v[2 * q] * inv));
        float q1 = 0.5f * tanh_fast(0.5f * (v[2 * q + 1] * inv));
        o2[t + q * 256] = __floats2bfloat162_rn(q0, q1);
    }
}

// ---------------- kernel 4: out[b,c,m] = x + base[c] - alpha * sum_n q*V ----
#define PV_STAGE_B ((128 * LDT + 256 * LDT) * 2)   // 55296 bytes per stage
#define PV_SMEM    (3 * PV_STAGE_B + 256)          // 166144
#define LDE 260
__global__ __launch_bounds__(256) void pv_wmma_kernel(const __nv_bfloat16* __restrict__ Aq,
                                                      const __nv_bfloat16* __restrict__ VH,
                                                      const float* __restrict__ xres,
                                                      const float* __restrict__ alpha,
                                                      float* __restrict__ out, int b) {
    extern __shared__ char dyn[];
    const int tid = threadIdx.x, w = tid >> 5;
    const int m0 = blockIdx.x * 128;

    uint32_t dynb = smem_u32(dyn);
    uint32_t base = (dynb + 255u) & ~255u;
    char* sb = dyn + (base - dynb);
    const uint32_t sbase = base;

    const __nv_bfloat16* pa = Aq + ((size_t)b * NPIX + m0) * (size_t)NPIX;
    const __nv_bfloat16* pb = VH + (size_t)b * CH * NPIX;

    auto issue_stage = [&](int t) {
        const int s = t % 3;
        const uint32_t dA = sbase + (uint32_t)s * PV_STAGE_B;
        const uint32_t dB = dA + 128 * LDT * 2;
        const int n0 = t << 6;
        #pragma unroll
        for (int p = 0; p < 4; ++p) {           // A: 128 rows x 64 bf16
            int idx = tid + p * 256;
            int row = idx >> 3, c8 = idx & 7;
            cpa16(dA + (uint32_t)(row * LDT + c8 * 8) * 2,
                  pa + (size_t)row * NPIX + n0 + c8 * 8);
        }
        #pragma unroll
        for (int p = 0; p < 8; ++p) {           // B: 256 rows x 64 bf16
            int idx = tid + p * 256;
            int row = idx >> 3, c8 = idx & 7;
            cpa16(dB + (uint32_t)(row * LDT + c8 * 8) * 2,
                  pb + (size_t)row * NPIX + n0 + c8 * 8);
        }
        cpa_commit();
    };

    const int wm = w >> 2;    // 0..1
    const int wc = w & 3;     // 0..3
    wmma::fragment<wmma::accumulator, 16, 16, 16, float> acc[4][4];
    #pragma unroll
    for (int mi = 0; mi < 4; ++mi)
        #pragma unroll
        for (int nj = 0; nj < 4; ++nj) wmma::fill_fragment(acc[mi][nj], 0.0f);

    issue_stage(0);
    issue_stage(1);

    for (int t = 0; t < 64; ++t) {
        if (t < 63) cpa_wait<1>(); else cpa_wait<0>();
        __syncthreads();

        const __nv_bfloat16* cA = (const __nv_bfloat16*)(sb + (size_t)(t % 3) * PV_STAGE_B);
        const __nv_bfloat16* cB = cA + 128 * LDT;
        #pragma unroll
        for (int kk = 0; kk < 64; kk += 16) {
            wmma::fragment<wmma::matrix_a, 16, 16, 16, __nv_bfloat16, wmma::row_major> af[4];
            #pragma unroll
            for (int mi = 0; mi < 4; ++mi)
                wmma::load_matrix_sync(af[mi], cA + (wm * 64 + mi * 16) * LDT + kk, LDT);
            #pragma unroll
            for (int nj = 0; nj < 4; ++nj) {
                wmma::fragment<wmma::matrix_b, 16, 16, 16, __nv_bfloat16, wmma::col_major> bf;
                wmma::load_matrix_sync(bf, cB + (wc * 64 + nj * 16) * LDT + kk, LDT);
                #pragma unroll
                for (int mi = 0; mi < 4; ++mi)
                    wmma::mma_sync(acc[mi][nj], af[mi], bf, acc[mi][nj]);
            }
        }

        if (t + 2 < 64) issue_stage(t + 2);
    }

    // epilogue: stage acc in smem, out = x + base[c] - alpha*acc
    __syncthreads();
    float* Sep = (float*)sb;                     // 128 * LDE * 4 = 133,120 B
    #pragma unroll
    for (int mi = 0; mi < 4; ++mi)
        #pragma unroll
        for (int nj = 0; nj < 4; ++nj)
            wmma::store_matrix_sync(Sep + (wm * 64 + mi * 16) * LDE + wc * 64 + nj * 16,
                                    acc[mi][nj], LDE, wmma::mem_row_major);
    __syncthreads();

    const float al = alpha[0];
    const int ml = tid & 127;
    const int ch = tid >> 7;                     // 0..1
    #pragma unroll 4
    for (int c2 = 0; c2 < 128; ++c2) {
        int c = ch * 128 + c2;
        size_t o = ((size_t)b * CH + c) * NPIX + m0 + ml;
        out[o] = xres[o] + g_base[b * CH + c] - al * Sep[ml * LDE + c];
    }
}

// ---------------- launch ----------------
extern "C" void kernel_launch(void* const* d_in, const int* in_sizes, int n_in,
                              void* d_out, int out_size) {
    const float* x1    = (const float*)d_in[0];
    const float* x2    = (const float*)d_in[1];
    const float* x     = (const float*)d_in[2];
    const float* gamma = (const float*)d_in[3];
    const float* beta  = (const float*)d_in[4];
    const float* mean  = (const float*)d_in[5];
    const float* var   = (const float*)d_in[6];
    const float* Wb    = (const float*)d_in[7];
    const float* bb    = (const float*)d_in[8];
    const float* Wc    = (const float*)d_in[9];
    const float* bc    = (const float*)d_in[10];
    const float* Wd    = (const float*)d_in[11];
    const float* bd    = (const float*)d_in[12];
    const float* alpha = (const float*)d_in[13];
    float* out = (float*)d_out;

    __nv_bfloat16 *Qp, *Kp, *VHp, *Aqp;
    __half* Sp;
    cudaGetSymbolAddress((void**)&Qp,  g_Qb);
    cudaGetSymbolAddress((void**)&Kp,  g_Kb);
    cudaGetSymbolAddress((void**)&VHp, g_VH);
    cudaGetSymbolAddress((void**)&Sp,  g_S);
    cudaGetSymbolAddress((void**)&Aqp, g_Aq);

    cudaFuncSetAttribute(qk_wmma_kernel, cudaFuncAttributeMaxDynamicSharedMemorySize, QK_SMEM);
    cudaFuncSetAttribute(pv_wmma_kernel, cudaFuncAttributeMaxDynamicSharedMemorySize, PV_SMEM);
    cudaFuncSetAttribute(projv_kernel,  cudaFuncAttributeMaxDynamicSharedMemorySize, PJV_SMEM);

    // fork all side/batch streams from capture root
    cudaEventRecord(g_evRoot, 0);
    cudaStreamWaitEvent(g_s2, g_evRoot, 0);
    for (int b = 0; b < BATCH; ++b) cudaStreamWaitEvent(g_sB[b], g_evRoot, 0);

    // side stream: Wd transpose -> V projection; colsum -> base
    transwd_kernel<<<CH, CH, 0, g_s2>>>(Wd);
    colsum_kernel<<<dim3(CH, BATCH), 256, 0, g_s2>>>(x);
    sumv_kernel<<<BATCH, CH, 0, g_s2>>>(Wd, bd, alpha);
    projv_kernel<<<dim3(NPIX / 128, CH / 128, BATCH), 256, PJV_SMEM, g_s2>>>(x, bd, VHp);
    cudaEventRecord(g_evJ, g_s2);

    // weight prep on default stream
    prep_kernel<<<1, 256>>>(gamma, beta, mean, var);
    foldw_kernel<<<dim3(CKDIM, 2), 256>>>(Wb, bb, Wc, bc);
    cudaEventRecord(g_evW, 0);

    // per-batch pipelines
    for (int b = 0; b < BATCH; ++b) {
        cudaStream_t s = g_sB[b];
        cudaStreamWaitEvent(s, g_evW, 0);
        projqk_kernel<<<dim3(NPIX / 128, 2), 256, 0, s>>>(x1, x2, Qp, Kp, b);
        qk_wmma_kernel<<<dim3(NPIX / 128, NPIX / 128), 256, QK_SMEM, s>>>(Qp, Kp, Sp, b);
        att_kernel<<<NPIX, 256, 0, s>>>(Sp, Aqp, b);
        cudaStreamWaitEvent(s, g_evJ, 0);
        pv_wmma_kernel<<<dim3(NPIX / 128), 256, PV_SMEM, s>>>(Aqp, VHp, x, alpha, out, b);
        cudaEventRecord(g_evB[b], s);
    }

    // join all batch streams into the capture stream
    for (int b = 0; b < BATCH; ++b) cudaStreamWaitEvent(0, g_evB[b], 0);
}